// round 6
// baseline (speedup 1.0000x reference)
#include <cuda_runtime.h>
#include <cstdint>

// Problem constants
#define B_  2
#define S_  2048
#define DM  768
#define H_  12
#define DK  64

// Scratch (allocation-free rule: device globals)
__device__ float g_Q[B_ * S_ * DM];
__device__ float g_K[B_ * S_ * DM];
__device__ float g_V[B_ * S_ * DM];
__device__ float g_X[B_ * S_ * DM];

// ---------------------------------------------------------------------------
// Packed fp32x2 helpers (sm_100+ PTX; SASS FFMA2 — 2 fp32 FMAs per issue)
// ---------------------------------------------------------------------------
typedef unsigned long long u64;

#define FMA2(d, a, b, c) \
    asm("fma.rn.f32x2 %0, %1, %2, %3;" : "=l"(d) : "l"(a), "l"(b), "l"(c))
#define MUL2(d, a, b) \
    asm("mul.rn.f32x2 %0, %1, %2;" : "=l"(d) : "l"(a), "l"(b))
#define PACK2(d, lo, hi) \
    asm("mov.b64 %0, {%1, %2};" : "=l"(d) : "f"(lo), "f"(hi))
#define UNPACK2(lo, hi, s) \
    asm("mov.b64 {%0, %1}, %2;" : "=f"(lo), "=f"(hi) : "l"(s))
#define LDS_V2B64(d0, d1, addr) \
    asm volatile("ld.shared.v2.b64 {%0, %1}, [%2];" \
                 : "=l"(d0), "=l"(d1) : "r"(addr))

// ---------------------------------------------------------------------------
// GEMM core: C[M,N] = A[M,K] @ W[N,K]^T + bias[N]
// 128x128 tile, BK=8, 256 threads, 8x8 microtile, double-buffered smem.
// FFMA2 with N-packed accumulators: B operand = natural u64 pair from the
// row-major Ws tile; A operand duplicated in smem ({a,a} pairs), read as
// 2-line broadcasts (ty-indexed -> conflict-free).
// ---------------------------------------------------------------------------
__device__ __forceinline__ void gemm_body(
    const float* __restrict__ A, const float* __restrict__ W,
    const float* __restrict__ bias, float* __restrict__ C,
    int M, int N, int K, int bm, int bn,
    float As2[2][8][256], float Ws[2][8][128])
{
    const int t  = threadIdx.x;
    const int tx = t & 15;        // N microtile (8 cols = 4 packed pairs)
    const int ty = t >> 4;        // M microtile (8 rows)

    const int lrow = t >> 1;        // 0..127
    const int lk   = (t & 1) * 4;   // 0 or 4

    // acc2[i][j2]: row ty*8+i, packed cols (tx*8+2*j2, tx*8+2*j2+1)
    u64 acc2[8][4];
#pragma unroll
    for (int i = 0; i < 8; i++)
#pragma unroll
        for (int j = 0; j < 4; j++) acc2[i][j] = 0ull;

    const float* Aptr = A + (size_t)(bm + lrow) * K + lk;
    const float* Wptr = W + (size_t)(bn + lrow) * K + lk;

    // stage tile 0
    {
        float4 av = *(const float4*)(Aptr);
        float4 wv = *(const float4*)(Wptr);
        *(float2*)&As2[0][lk + 0][2 * lrow] = make_float2(av.x, av.x);
        *(float2*)&As2[0][lk + 1][2 * lrow] = make_float2(av.y, av.y);
        *(float2*)&As2[0][lk + 2][2 * lrow] = make_float2(av.z, av.z);
        *(float2*)&As2[0][lk + 3][2 * lrow] = make_float2(av.w, av.w);
        Ws[0][lk + 0][lrow] = wv.x; Ws[0][lk + 1][lrow] = wv.y;
        Ws[0][lk + 2][lrow] = wv.z; Ws[0][lk + 3][lrow] = wv.w;
    }
    __syncthreads();

    const uint32_t aB0 = (uint32_t)__cvta_generic_to_shared(&As2[0][0][ty * 16]);
    const uint32_t aB1 = (uint32_t)__cvta_generic_to_shared(&As2[1][0][ty * 16]);
    const uint32_t bB0 = (uint32_t)__cvta_generic_to_shared(&Ws[0][0][tx * 8]);
    const uint32_t bB1 = (uint32_t)__cvta_generic_to_shared(&Ws[1][0][tx * 8]);

    int cur = 0;
    for (int kt = 0; kt < K; kt += 8) {
        const bool has_next = (kt + 8) < K;
        float4 av2, wv2;
        if (has_next) {
            av2 = *(const float4*)(Aptr + kt + 8);
            wv2 = *(const float4*)(Wptr + kt + 8);
        }

        const uint32_t aB = cur ? aB1 : aB0;
        const uint32_t bB = cur ? bB1 : bB0;
#pragma unroll
        for (int k = 0; k < 8; k++) {
            u64 a2[8], b2[4];
            LDS_V2B64(a2[0], a2[1], aB + k * 1024 + 0);
            LDS_V2B64(a2[2], a2[3], aB + k * 1024 + 16);
            LDS_V2B64(a2[4], a2[5], aB + k * 1024 + 32);
            LDS_V2B64(a2[6], a2[7], aB + k * 1024 + 48);
            LDS_V2B64(b2[0], b2[1], bB + k * 512 + 0);
            LDS_V2B64(b2[2], b2[3], bB + k * 512 + 16);
#pragma unroll
            for (int i = 0; i < 8; i++)
#pragma unroll
                for (int j = 0; j < 4; j++)
                    FMA2(acc2[i][j], a2[i], b2[j], acc2[i][j]);
        }

        if (has_next) {
            const int nxt = cur ^ 1;
            *(float2*)&As2[nxt][lk + 0][2 * lrow] = make_float2(av2.x, av2.x);
            *(float2*)&As2[nxt][lk + 1][2 * lrow] = make_float2(av2.y, av2.y);
            *(float2*)&As2[nxt][lk + 2][2 * lrow] = make_float2(av2.z, av2.z);
            *(float2*)&As2[nxt][lk + 3][2 * lrow] = make_float2(av2.w, av2.w);
            Ws[nxt][lk + 0][lrow] = wv2.x; Ws[nxt][lk + 1][lrow] = wv2.y;
            Ws[nxt][lk + 2][lrow] = wv2.z; Ws[nxt][lk + 3][lrow] = wv2.w;
        }
        __syncthreads();
        cur ^= 1;
    }

    float bv[8];
#pragma unroll
    for (int j = 0; j < 8; j++) bv[j] = bias[bn + tx * 8 + j];

#pragma unroll
    for (int i = 0; i < 8; i++) {
        float c0, c1, c2, c3, c4, c5, c6, c7;
        UNPACK2(c0, c1, acc2[i][0]);
        UNPACK2(c2, c3, acc2[i][1]);
        UNPACK2(c4, c5, acc2[i][2]);
        UNPACK2(c6, c7, acc2[i][3]);
        float* crow = C + (size_t)(bm + ty * 8 + i) * N + bn + tx * 8;
        float4 o0 = { c0 + bv[0], c1 + bv[1], c2 + bv[2], c3 + bv[3] };
        float4 o1 = { c4 + bv[4], c5 + bv[5], c6 + bv[6], c7 + bv[7] };
        *(float4*)(crow + 0) = o0;
        *(float4*)(crow + 4) = o1;
    }
}

// Fused QKV: blockIdx.x in [0,18): [0,6)->Q, [6,12)->K, [12,18)->V.
__global__ __launch_bounds__(256) void gemm_qkv(
    const float* __restrict__ q, const float* __restrict__ k,
    const float* __restrict__ v,
    const float* __restrict__ wq, const float* __restrict__ bq,
    const float* __restrict__ wk, const float* __restrict__ bk,
    const float* __restrict__ wv, const float* __restrict__ bv,
    float* __restrict__ gQ, float* __restrict__ gK, float* __restrict__ gV)
{
    __shared__ float As2[2][8][256];
    __shared__ float Ws[2][8][128];

    const int bx  = blockIdx.x;
    const int sel = bx / 6;
    const int bn  = (bx % 6) * 128;
    const int bm  = blockIdx.y * 128;

    const float* A; const float* W; const float* bias; float* C;
    if (sel == 0)      { A = q; W = wq; bias = bq; C = gQ; }
    else if (sel == 1) { A = k; W = wk; bias = bk; C = gK; }
    else               { A = v; W = wv; bias = bv; C = gV; }

    gemm_body(A, W, bias, C, B_ * S_, DM, DM, bm, bn, As2, Ws);
}

__global__ __launch_bounds__(256) void gemm_nt_bias(
    const float* __restrict__ A, const float* __restrict__ W,
    const float* __restrict__ bias, float* __restrict__ C,
    int M, int N, int K)
{
    __shared__ float As2[2][8][256];
    __shared__ float Ws[2][8][128];
    gemm_body(A, W, bias, C, M, N, K,
              blockIdx.y * 128, blockIdx.x * 128, As2, Ws);
}

// ---------------------------------------------------------------------------
// Causal flash attention v4: dim-split — 2 threads per query (32 dims each),
// 64 queries per 128-thread block, fp32x2 math, 16-key chunks.
// Score merged across the pair with one shfl.bfly per key (pair mask: the
// remainder loop is divergent across queries, but pair lanes always agree).
// ---------------------------------------------------------------------------
template<bool MASKED>
__device__ __forceinline__ void process16(
    uint32_t ksC, uint32_t vsC,          // this thread's half-offset chunk base
    const u64* __restrict__ q2, u64* __restrict__ o2,
    float& m, float& l, int rel_end, unsigned pmask)
{
    u64 s2[16];
#pragma unroll
    for (int j = 0; j < 16; j++) s2[j] = 0ull;

    // Partial scores over this thread's 32 dims: dd-outer, j-inner.
#pragma unroll
    for (int dd = 0; dd < 8; dd++) {
        const u64 qa = q2[2 * dd], qb = q2[2 * dd + 1];
#pragma unroll
        for (int j = 0; j < 16; j++) {
            u64 ka, kb;
            LDS_V2B64(ka, kb, ksC + j * 256 + dd * 16);
            FMA2(s2[j], qa, ka, s2[j]);
            FMA2(s2[j], qb, kb, s2[j]);
        }
    }

    float s[16];
    float cmax = -1e30f;
#pragma unroll
    for (int j = 0; j < 16; j++) {
        float lo, hi;
        UNPACK2(lo, hi, s2[j]);
        const float ph   = lo + hi;
        const float full = ph + __shfl_xor_sync(pmask, ph, 1);
        float sj = full * 0.125f;                 // 1/sqrt(64)
        if (MASKED) { if (j >= rel_end) sj = -1e30f; }
        s[j] = sj;
        cmax = fmaxf(cmax, sj);
    }

    const float newm = fmaxf(m, cmax);
    const float corr = __expf(m - newm);          // 0 on first chunk
    m = newm;
    l *= corr;
    u64 corr2; PACK2(corr2, corr, corr);
#pragma unroll
    for (int d = 0; d < 16; d++) MUL2(o2[d], o2[d], corr2);

    float lsum = 0.f;
#pragma unroll
    for (int j = 0; j < 16; j++) {
        s[j] = __expf(s[j] - newm);               // masked -> 0
        lsum += s[j];
    }
    l += lsum;

    // PV over this thread's 32 dims.
#pragma unroll
    for (int j = 0; j < 16; j++) {
        u64 p2; PACK2(p2, s[j], s[j]);
#pragma unroll
        for (int dd = 0; dd < 8; dd++) {
            u64 va, vb;
            LDS_V2B64(va, vb, vsC + j * 256 + dd * 16);
            FMA2(o2[2 * dd],     p2, va, o2[2 * dd]);
            FMA2(o2[2 * dd + 1], p2, vb, o2[2 * dd + 1]);
        }
    }
}

__global__ __launch_bounds__(128, 3) void attn_kernel(
    const float* __restrict__ Q, const float* __restrict__ K,
    const float* __restrict__ V, float* __restrict__ X)
{
    __shared__ float Ks[64 * 64];
    __shared__ float Vs[64 * 64];

    const int tid  = threadIdx.x;
    const int half = tid & 1;            // which 32 dims
    const int ql   = tid >> 1;           // query within block (0..63)
    const int h    = blockIdx.y;
    const int b    = blockIdx.z;
    const int qblk = (int)gridDim.x - 1 - (int)blockIdx.x;   // LPT order
    const int q0   = qblk * 64;
    const int qi   = q0 + ql;
    const unsigned pmask = 3u << (tid & 30);   // pair {even,odd} lane mask

    const uint32_t ksBase = (uint32_t)__cvta_generic_to_shared(Ks) + half * 128;
    const uint32_t vsBase = (uint32_t)__cvta_generic_to_shared(Vs) + half * 128;

    // Load this thread's 32 query dims as 16 packed pairs.
    u64 q2[16];
    {
        const ulonglong2* qp = (const ulonglong2*)
            (Q + ((size_t)(b * S_ + qi)) * DM + h * DK + half * 32);
#pragma unroll
        for (int i = 0; i < 8; i++) {
            ulonglong2 t2 = qp[i];
            q2[2 * i] = t2.x; q2[2 * i + 1] = t2.y;
        }
    }

    u64 o2[16];
#pragma unroll
    for (int d = 0; d < 16; d++) o2[d] = 0ull;
    float m = -1e30f, l = 0.f;

    const int kmax = q0 + 64;

    for (int c0 = 0; c0 < kmax; c0 += 64) {
        const float4* kb4 = (const float4*)(K + ((size_t)(b * S_ + c0)) * DM + h * DK);
        const float4* vb4 = (const float4*)(V + ((size_t)(b * S_ + c0)) * DM + h * DK);
#pragma unroll
        for (int i = 0; i < 8; i++) {
            const int idx = tid + i * 128;        // 0..1023
            const int j   = idx >> 4;
            const int cc  = idx & 15;
            ((float4*)Ks)[idx] = kb4[(size_t)j * (DM / 4) + cc];
            ((float4*)Vs)[idx] = vb4[(size_t)j * (DM / 4) + cc];
        }
        __syncthreads();

        int jend = qi - c0 + 1;
        if (jend > 64) jend = 64;

        int jb = 0;
        for (; jb + 16 <= jend; jb += 16)
            process16<false>(ksBase + jb * 256, vsBase + jb * 256,
                             q2, o2, m, l, 16, pmask);
        const int rem = jend - jb;
        if (rem > 0)
            process16<true>(ksBase + jb * 256, vsBase + jb * 256,
                            q2, o2, m, l, rem, pmask);
        __syncthreads();
    }

    const float inv = 1.f / l;
    u64 inv2; PACK2(inv2, inv, inv);
    ulonglong2* xp = (ulonglong2*)
        (X + ((size_t)(b * S_ + qi)) * DM + h * DK + half * 32);
#pragma unroll
    for (int i = 0; i < 8; i++) {
        u64 r0, r1;
        MUL2(r0, o2[2 * i],     inv2);
        MUL2(r1, o2[2 * i + 1], inv2);
        ulonglong2 t2; t2.x = r0; t2.y = r1;
        xp[i] = t2;
    }
}

// ---------------------------------------------------------------------------
// Launch
// Inputs: 0:q 1:k 2:v 3:mask 4:wq 5:bq 6:wk 7:bk 8:wv 9:bv 10:wo 11:bo
// ---------------------------------------------------------------------------
extern "C" void kernel_launch(void* const* d_in, const int* in_sizes, int n_in,
                              void* d_out, int out_size)
{
    const float* q  = (const float*)d_in[0];
    const float* k  = (const float*)d_in[1];
    const float* v  = (const float*)d_in[2];
    const float* wq = (const float*)d_in[4];
    const float* bq = (const float*)d_in[5];
    const float* wk = (const float*)d_in[6];
    const float* bk = (const float*)d_in[7];
    const float* wv = (const float*)d_in[8];
    const float* bv = (const float*)d_in[9];
    const float* wo = (const float*)d_in[10];
    const float* bo = (const float*)d_in[11];
    float* out = (float*)d_out;

    float *gQ, *gK, *gV, *gX;
    cudaGetSymbolAddress((void**)&gQ, g_Q);
    cudaGetSymbolAddress((void**)&gK, g_K);
    cudaGetSymbolAddress((void**)&gV, g_V);
    cudaGetSymbolAddress((void**)&gX, g_X);

    const int M = B_ * S_;  // 4096

    dim3 qkvgrid(18, M / 128);       // (18, 32) fused QKV
    gemm_qkv<<<qkvgrid, 256>>>(q, k, v, wq, bq, wk, bk, wv, bv, gQ, gK, gV);

    dim3 agrid(S_ / 64, H_, B_);     // (32, 12, 2) — 64 queries/block
    attn_kernel<<<agrid, 128>>>(gQ, gK, gV, gX);

    dim3 ggrid(DM / 128, M / 128);   // (6, 32)
    gemm_nt_bias<<<ggrid, 256>>>(gX, wo, bo, out, M, DM, DM);
}

// round 7
// speedup vs baseline: 1.1177x; 1.1177x over previous
#include <cuda_runtime.h>
#include <cstdint>

// Problem constants
#define B_  2
#define S_  2048
#define DM  768
#define H_  12
#define DK  64

// Scratch (allocation-free rule: device globals)
__device__ float g_Q[B_ * S_ * DM];
__device__ float g_K[B_ * S_ * DM];
__device__ float g_V[B_ * S_ * DM];
__device__ float g_X[B_ * S_ * DM];

// ---------------------------------------------------------------------------
// Packed fp32x2 helpers (sm_100+ PTX; SASS FFMA2) — attention only.
// ---------------------------------------------------------------------------
typedef unsigned long long u64;

#define FMA2(d, a, b, c) \
    asm("fma.rn.f32x2 %0, %1, %2, %3;" : "=l"(d) : "l"(a), "l"(b), "l"(c))
#define MUL2(d, a, b) \
    asm("mul.rn.f32x2 %0, %1, %2;" : "=l"(d) : "l"(a), "l"(b))
#define PACK2(d, lo, hi) \
    asm("mov.b64 %0, {%1, %2};" : "=l"(d) : "f"(lo), "f"(hi))
#define UNPACK2(lo, hi, s) \
    asm("mov.b64 {%0, %1}, %2;" : "=f"(lo), "=f"(hi) : "l"(s))
#define LDS_V2B64(d0, d1, addr) \
    asm volatile("ld.shared.v2.b64 {%0, %1}, [%2];" \
                 : "=l"(d0), "=l"(d1) : "r"(addr))
// Un-hoistable 16B global load as two packed f32 pairs (little-endian).
#define LDG_V2B64(d0, d1, ptr) \
    asm volatile("ld.global.nc.v2.b64 {%0, %1}, [%2];" \
                 : "=l"(d0), "=l"(d1) : "l"(ptr))

// ---------------------------------------------------------------------------
// GEMM core (R4 proven version): C[M,N] = A[M,K] @ W[N,K]^T + bias[N]
// 128x128 tile, BK=8, 256 threads, 8x8 microtile, double-buffered smem,
// plain FFMA.
// ---------------------------------------------------------------------------
__device__ __forceinline__ void gemm_body(
    const float* __restrict__ A, const float* __restrict__ W,
    const float* __restrict__ bias, float* __restrict__ C,
    int M, int N, int K, int bm, int bn,
    float As[2][8][128], float Ws[2][8][128])
{
    const int t  = threadIdx.x;
    const int tx = t & 15;        // N microtile
    const int ty = t >> 4;        // M microtile

    const int lrow = t >> 1;        // 0..127
    const int lk   = (t & 1) * 4;   // 0 or 4

    float acc[8][8];
#pragma unroll
    for (int i = 0; i < 8; i++)
#pragma unroll
        for (int j = 0; j < 8; j++) acc[i][j] = 0.f;

    const float* Aptr = A + (size_t)(bm + lrow) * K + lk;
    const float* Wptr = W + (size_t)(bn + lrow) * K + lk;

    // preload tile 0
    {
        float4 av = *(const float4*)(Aptr);
        float4 wv = *(const float4*)(Wptr);
        As[0][lk + 0][lrow] = av.x; As[0][lk + 1][lrow] = av.y;
        As[0][lk + 2][lrow] = av.z; As[0][lk + 3][lrow] = av.w;
        Ws[0][lk + 0][lrow] = wv.x; Ws[0][lk + 1][lrow] = wv.y;
        Ws[0][lk + 2][lrow] = wv.z; Ws[0][lk + 3][lrow] = wv.w;
    }
    __syncthreads();

    int cur = 0;
    for (int kt = 0; kt < K; kt += 8) {
        const bool has_next = (kt + 8) < K;
        float4 av2, wv2;
        if (has_next) {
            av2 = *(const float4*)(Aptr + kt + 8);
            wv2 = *(const float4*)(Wptr + kt + 8);
        }

#pragma unroll
        for (int k = 0; k < 8; k++) {
            float a[8], b[8];
            *(float4*)&a[0] = *(const float4*)&As[cur][k][ty * 8 + 0];
            *(float4*)&a[4] = *(const float4*)&As[cur][k][ty * 8 + 4];
            *(float4*)&b[0] = *(const float4*)&Ws[cur][k][tx * 8 + 0];
            *(float4*)&b[4] = *(const float4*)&Ws[cur][k][tx * 8 + 4];
#pragma unroll
            for (int i = 0; i < 8; i++)
#pragma unroll
                for (int j = 0; j < 8; j++)
                    acc[i][j] = fmaf(a[i], b[j], acc[i][j]);
        }

        if (has_next) {
            const int nxt = cur ^ 1;
            As[nxt][lk + 0][lrow] = av2.x; As[nxt][lk + 1][lrow] = av2.y;
            As[nxt][lk + 2][lrow] = av2.z; As[nxt][lk + 3][lrow] = av2.w;
            Ws[nxt][lk + 0][lrow] = wv2.x; Ws[nxt][lk + 1][lrow] = wv2.y;
            Ws[nxt][lk + 2][lrow] = wv2.z; Ws[nxt][lk + 3][lrow] = wv2.w;
        }
        __syncthreads();
        cur ^= 1;
    }

    float bv[8];
#pragma unroll
    for (int j = 0; j < 8; j++) bv[j] = bias[bn + tx * 8 + j];

#pragma unroll
    for (int i = 0; i < 8; i++) {
        float* crow = C + (size_t)(bm + ty * 8 + i) * N + bn + tx * 8;
        float4 o0 = { acc[i][0] + bv[0], acc[i][1] + bv[1],
                      acc[i][2] + bv[2], acc[i][3] + bv[3] };
        float4 o1 = { acc[i][4] + bv[4], acc[i][5] + bv[5],
                      acc[i][6] + bv[6], acc[i][7] + bv[7] };
        *(float4*)(crow + 0) = o0;
        *(float4*)(crow + 4) = o1;
    }
}

// Fused QKV: blockIdx.x in [0,18): [0,6)->Q, [6,12)->K, [12,18)->V.
__global__ __launch_bounds__(256) void gemm_qkv(
    const float* __restrict__ q, const float* __restrict__ k,
    const float* __restrict__ v,
    const float* __restrict__ wq, const float* __restrict__ bq,
    const float* __restrict__ wk, const float* __restrict__ bk,
    const float* __restrict__ wv, const float* __restrict__ bv,
    float* __restrict__ gQ, float* __restrict__ gK, float* __restrict__ gV)
{
    __shared__ float As[2][8][128];
    __shared__ float Ws[2][8][128];

    const int bx  = blockIdx.x;
    const int sel = bx / 6;
    const int bn  = (bx % 6) * 128;
    const int bm  = blockIdx.y * 128;

    const float* A; const float* W; const float* bias; float* C;
    if (sel == 0)      { A = q; W = wq; bias = bq; C = gQ; }
    else if (sel == 1) { A = k; W = wk; bias = bk; C = gK; }
    else               { A = v; W = wv; bias = bv; C = gV; }

    gemm_body(A, W, bias, C, B_ * S_, DM, DM, bm, bn, As, Ws);
}

__global__ __launch_bounds__(256) void gemm_nt_bias(
    const float* __restrict__ A, const float* __restrict__ W,
    const float* __restrict__ bias, float* __restrict__ C,
    int M, int N, int K)
{
    __shared__ float As[2][8][128];
    __shared__ float Ws[2][8][128];
    gemm_body(A, W, bias, C, M, N, K,
              blockIdx.y * 128, blockIdx.x * 128, As, Ws);
}

// ---------------------------------------------------------------------------
// Causal flash attention v5: R3 structure (1 thread/query, 16-key chunks,
// fp32x2 math) but q STREAMED from global inside the score loop instead of
// held in registers. Drops ~64 regs -> 3 CTAs/SM -> single wave of 384.
// q loads are L1-resident after chunk 0 (32KB/CTA working set).
// ---------------------------------------------------------------------------
template<bool MASKED>
__device__ __forceinline__ void process16(
    uint32_t ksC, uint32_t vsC,
    const float* __restrict__ qptr,      // this thread's 64-dim query row
    u64* __restrict__ o2,
    float& m, float& l, int rel_end)
{
    u64 s2[16];
#pragma unroll
    for (int j = 0; j < 16; j++) s2[j] = 0ull;

    // Scores: d4-outer (stream q 16B at a time), j-inner -> 16 chains.
#pragma unroll
    for (int d4 = 0; d4 < 16; d4++) {
        u64 qa, qb;
        LDG_V2B64(qa, qb, qptr + d4 * 4);
#pragma unroll
        for (int j = 0; j < 16; j++) {
            u64 ka, kb;
            LDS_V2B64(ka, kb, ksC + j * 256 + d4 * 16);
            FMA2(s2[j], qa, ka, s2[j]);
            FMA2(s2[j], qb, kb, s2[j]);
        }
    }

    float s[16];
    float cmax = -1e30f;
#pragma unroll
    for (int j = 0; j < 16; j++) {
        float lo, hi;
        UNPACK2(lo, hi, s2[j]);
        float sj = (lo + hi) * 0.125f;            // 1/sqrt(64)
        if (MASKED) { if (j >= rel_end) sj = -1e30f; }
        s[j] = sj;
        cmax = fmaxf(cmax, sj);
    }

    const float newm = fmaxf(m, cmax);
    const float corr = __expf(m - newm);          // 0 on first chunk
    m = newm;
    l *= corr;
    u64 corr2; PACK2(corr2, corr, corr);
#pragma unroll
    for (int d = 0; d < 32; d++) MUL2(o2[d], o2[d], corr2);

    float lsum = 0.f;
#pragma unroll
    for (int j = 0; j < 16; j++) {
        s[j] = __expf(s[j] - newm);               // masked -> 0
        lsum += s[j];
    }
    l += lsum;

    // PV: j-outer, d-inner.
#pragma unroll
    for (int j = 0; j < 16; j++) {
        u64 p2; PACK2(p2, s[j], s[j]);
#pragma unroll
        for (int d = 0; d < 16; d++) {
            u64 va, vb;
            LDS_V2B64(va, vb, vsC + j * 256 + d * 16);
            FMA2(o2[2 * d],     p2, va, o2[2 * d]);
            FMA2(o2[2 * d + 1], p2, vb, o2[2 * d + 1]);
        }
    }
}

__global__ __launch_bounds__(128, 3) void attn_kernel(
    const float* __restrict__ Q, const float* __restrict__ K,
    const float* __restrict__ V, float* __restrict__ X)
{
    __shared__ float Ks[64 * 64];
    __shared__ float Vs[64 * 64];

    const int tid = threadIdx.x;
    const int h   = blockIdx.y;
    const int b   = blockIdx.z;
    const int qblk = (int)gridDim.x - 1 - (int)blockIdx.x;   // LPT order
    const int q0   = qblk * 128;
    const int qi   = q0 + tid;

    const uint32_t ksBase = (uint32_t)__cvta_generic_to_shared(Ks);
    const uint32_t vsBase = (uint32_t)__cvta_generic_to_shared(Vs);

    const float* qptr = Q + ((size_t)(b * S_ + qi)) * DM + h * DK;

    u64 o2[32];
#pragma unroll
    for (int d = 0; d < 32; d++) o2[d] = 0ull;
    float m = -1e30f, l = 0.f;

    const int kmax = q0 + 128;

    for (int c0 = 0; c0 < kmax; c0 += 64) {
        const float4* kb4 = (const float4*)(K + ((size_t)(b * S_ + c0)) * DM + h * DK);
        const float4* vb4 = (const float4*)(V + ((size_t)(b * S_ + c0)) * DM + h * DK);
#pragma unroll
        for (int i = 0; i < 8; i++) {
            const int idx = tid + i * 128;        // 0..1023
            const int j   = idx >> 4;
            const int cc  = idx & 15;
            ((float4*)Ks)[idx] = kb4[(size_t)j * (DM / 4) + cc];
            ((float4*)Vs)[idx] = vb4[(size_t)j * (DM / 4) + cc];
        }
        __syncthreads();

        int jend = qi - c0 + 1;
        if (jend > 64) jend = 64;

        int jb = 0;
        for (; jb + 16 <= jend; jb += 16)
            process16<false>(ksBase + jb * 256, vsBase + jb * 256,
                             qptr, o2, m, l, 16);
        const int rem = jend - jb;
        if (rem > 0)
            process16<true>(ksBase + jb * 256, vsBase + jb * 256,
                            qptr, o2, m, l, rem);
        __syncthreads();
    }

    const float inv = 1.f / l;
    float* xptr = X + ((size_t)(b * S_ + qi)) * DM + h * DK;
#pragma unroll
    for (int d = 0; d < 16; d++) {
        float a0, a1, a2, a3;
        UNPACK2(a0, a1, o2[2 * d]);
        UNPACK2(a2, a3, o2[2 * d + 1]);
        float4 ov = { a0 * inv, a1 * inv, a2 * inv, a3 * inv };
        *(float4*)(xptr + d * 4) = ov;
    }
}

// ---------------------------------------------------------------------------
// Launch
// Inputs: 0:q 1:k 2:v 3:mask 4:wq 5:bq 6:wk 7:bk 8:wv 9:bv 10:wo 11:bo
// ---------------------------------------------------------------------------
extern "C" void kernel_launch(void* const* d_in, const int* in_sizes, int n_in,
                              void* d_out, int out_size)
{
    const float* q  = (const float*)d_in[0];
    const float* k  = (const float*)d_in[1];
    const float* v  = (const float*)d_in[2];
    const float* wq = (const float*)d_in[4];
    const float* bq = (const float*)d_in[5];
    const float* wk = (const float*)d_in[6];
    const float* bk = (const float*)d_in[7];
    const float* wv = (const float*)d_in[8];
    const float* bv = (const float*)d_in[9];
    const float* wo = (const float*)d_in[10];
    const float* bo = (const float*)d_in[11];
    float* out = (float*)d_out;

    float *gQ, *gK, *gV, *gX;
    cudaGetSymbolAddress((void**)&gQ, g_Q);
    cudaGetSymbolAddress((void**)&gK, g_K);
    cudaGetSymbolAddress((void**)&gV, g_V);
    cudaGetSymbolAddress((void**)&gX, g_X);

    const int M = B_ * S_;  // 4096

    dim3 qkvgrid(18, M / 128);       // (18, 32) fused QKV
    gemm_qkv<<<qkvgrid, 256>>>(q, k, v, wq, bq, wk, bk, wv, bv, gQ, gK, gV);

    dim3 agrid(S_ / 128, H_, B_);    // (16, 12, 2)
    attn_kernel<<<agrid, 128>>>(gQ, gK, gV, gX);

    dim3 ggrid(DM / 128, M / 128);   // (6, 32)
    gemm_nt_bias<<<ggrid, 256>>>(gX, wo, bo, out, M, DM, DM);
}

// round 9
// speedup vs baseline: 1.3533x; 1.2107x over previous
#include <cuda_runtime.h>
#include <cstdint>

// Problem constants
#define B_  2
#define S_  2048
#define DM  768
#define H_  12
#define DK  64

// Scratch (allocation-free rule: device globals)
__device__ float g_Q[B_ * S_ * DM];
__device__ float g_K[B_ * S_ * DM];
__device__ float g_V[B_ * S_ * DM];
__device__ float g_X[B_ * S_ * DM];

// ---------------------------------------------------------------------------
// Packed fp32x2 helpers (sm_100+ PTX; SASS FFMA2 — 2 fp32 FMAs per issue)
// ---------------------------------------------------------------------------
typedef unsigned long long u64;

#define FMA2(d, a, b, c) \
    asm("fma.rn.f32x2 %0, %1, %2, %3;" : "=l"(d) : "l"(a), "l"(b), "l"(c))
#define MUL2(d, a, b) \
    asm("mul.rn.f32x2 %0, %1, %2;" : "=l"(d) : "l"(a), "l"(b))
#define PACK2(d, lo, hi) \
    asm("mov.b64 %0, {%1, %2};" : "=l"(d) : "f"(lo), "f"(hi))
#define UNPACK2(lo, hi, s) \
    asm("mov.b64 {%0, %1}, %2;" : "=f"(lo), "=f"(hi) : "l"(s))
#define LDS_V2B64(d0, d1, addr) \
    asm volatile("ld.shared.v2.b64 {%0, %1}, [%2];" \
                 : "=l"(d0), "=l"(d1) : "r"(addr))

// ---------------------------------------------------------------------------
// GEMM: C[M,N] = A[M,K] @ W[N,K]^T + bias[N]
// 128x128 tile, BK=8, 256 threads, 8x8 microtile, double-buffered smem
// (UNCHANGED 16KB layout from the proven R4 kernel). Inner loop uses FFMA2:
// accumulators packed over adjacent M rows (natural u64 pairs from As),
// B values duplicated into {b,b} pairs in REGISTERS (alu-pipe MOVs).
// ---------------------------------------------------------------------------
__device__ __forceinline__ void gemm_body(
    const float* __restrict__ A, const float* __restrict__ W,
    const float* __restrict__ bias, float* __restrict__ C,
    int M, int N, int K, int bm, int bn,
    float As[2][8][128], float Ws[2][8][128])
{
    const int t  = threadIdx.x;
    const int tx = t & 15;        // N microtile
    const int ty = t >> 4;        // M microtile

    const int lrow = t >> 1;        // 0..127
    const int lk   = (t & 1) * 4;   // 0 or 4

    // acc2[i2][j]: packed rows (ty*8+2*i2, ty*8+2*i2+1), col tx*8+j
    u64 acc2[4][8];
#pragma unroll
    for (int i = 0; i < 4; i++)
#pragma unroll
        for (int j = 0; j < 8; j++) acc2[i][j] = 0ull;

    const float* Aptr = A + (size_t)(bm + lrow) * K + lk;
    const float* Wptr = W + (size_t)(bn + lrow) * K + lk;

    // preload tile 0
    {
        float4 av = *(const float4*)(Aptr);
        float4 wv = *(const float4*)(Wptr);
        As[0][lk + 0][lrow] = av.x; As[0][lk + 1][lrow] = av.y;
        As[0][lk + 2][lrow] = av.z; As[0][lk + 3][lrow] = av.w;
        Ws[0][lk + 0][lrow] = wv.x; Ws[0][lk + 1][lrow] = wv.y;
        Ws[0][lk + 2][lrow] = wv.z; Ws[0][lk + 3][lrow] = wv.w;
    }
    __syncthreads();

    const uint32_t aB0 = (uint32_t)__cvta_generic_to_shared(&As[0][0][ty * 8]);
    const uint32_t aB1 = (uint32_t)__cvta_generic_to_shared(&As[1][0][ty * 8]);
    const uint32_t bB0 = (uint32_t)__cvta_generic_to_shared(&Ws[0][0][tx * 8]);
    const uint32_t bB1 = (uint32_t)__cvta_generic_to_shared(&Ws[1][0][tx * 8]);

    int cur = 0;
    for (int kt = 0; kt < K; kt += 8) {
        const bool has_next = (kt + 8) < K;
        float4 av2, wv2;
        if (has_next) {
            av2 = *(const float4*)(Aptr + kt + 8);
            wv2 = *(const float4*)(Wptr + kt + 8);
        }

        const uint32_t aB = cur ? aB1 : aB0;
        const uint32_t bB = cur ? bB1 : bB0;
#pragma unroll
        for (int k = 0; k < 8; k++) {
            // A: 8 rows = 4 natural packed pairs (adjacent smem floats).
            u64 a2[4];
            LDS_V2B64(a2[0], a2[1], aB + k * 512);
            LDS_V2B64(a2[2], a2[3], aB + k * 512 + 16);
            // B: 8 floats, duplicated into {b,b} pairs in registers.
            float b[8];
            *(float4*)&b[0] = *(const float4*)((const char*)0 + 0, &Ws[cur][k][tx * 8 + 0]), *(const float4*)&Ws[cur][k][tx * 8 + 0];
            *(float4*)&b[4] = *(const float4*)&Ws[cur][k][tx * 8 + 4];
            (void)bB;
            u64 b2[8];
#pragma unroll
            for (int j = 0; j < 8; j++) PACK2(b2[j], b[j], b[j]);
#pragma unroll
            for (int j = 0; j < 8; j++)
#pragma unroll
                for (int i = 0; i < 4; i++)
                    FMA2(acc2[i][j], a2[i], b2[j], acc2[i][j]);
        }

        if (has_next) {
            const int nxt = cur ^ 1;
            As[nxt][lk + 0][lrow] = av2.x; As[nxt][lk + 1][lrow] = av2.y;
            As[nxt][lk + 2][lrow] = av2.z; As[nxt][lk + 3][lrow] = av2.w;
            Ws[nxt][lk + 0][lrow] = wv2.x; Ws[nxt][lk + 1][lrow] = wv2.y;
            Ws[nxt][lk + 2][lrow] = wv2.z; Ws[nxt][lk + 3][lrow] = wv2.w;
        }
        __syncthreads();
        cur ^= 1;
    }

    float bv[8];
#pragma unroll
    for (int j = 0; j < 8; j++) bv[j] = bias[bn + tx * 8 + j];

#pragma unroll
    for (int i2 = 0; i2 < 4; i2++) {
        float lo[8], hi[8];
#pragma unroll
        for (int j = 0; j < 8; j++) UNPACK2(lo[j], hi[j], acc2[i2][j]);

        float* r0 = C + (size_t)(bm + ty * 8 + 2 * i2 + 0) * N + bn + tx * 8;
        float* r1 = C + (size_t)(bm + ty * 8 + 2 * i2 + 1) * N + bn + tx * 8;
        float4 o0 = { lo[0] + bv[0], lo[1] + bv[1], lo[2] + bv[2], lo[3] + bv[3] };
        float4 o1 = { lo[4] + bv[4], lo[5] + bv[5], lo[6] + bv[6], lo[7] + bv[7] };
        float4 o2 = { hi[0] + bv[0], hi[1] + bv[1], hi[2] + bv[2], hi[3] + bv[3] };
        float4 o3 = { hi[4] + bv[4], hi[5] + bv[5], hi[6] + bv[6], hi[7] + bv[7] };
        *(float4*)(r0 + 0) = o0;
        *(float4*)(r0 + 4) = o1;
        *(float4*)(r1 + 0) = o2;
        *(float4*)(r1 + 4) = o3;
    }
}

// Fused QKV: blockIdx.x in [0,18): [0,6)->Q, [6,12)->K, [12,18)->V.
__global__ __launch_bounds__(256, 2) void gemm_qkv(
    const float* __restrict__ q, const float* __restrict__ k,
    const float* __restrict__ v,
    const float* __restrict__ wq, const float* __restrict__ bq,
    const float* __restrict__ wk, const float* __restrict__ bk,
    const float* __restrict__ wv, const float* __restrict__ bv,
    float* __restrict__ gQ, float* __restrict__ gK, float* __restrict__ gV)
{
    __shared__ float As[2][8][128];
    __shared__ float Ws[2][8][128];

    const int bx  = blockIdx.x;
    const int sel = bx / 6;
    const int bn  = (bx % 6) * 128;
    const int bm  = blockIdx.y * 128;

    const float* A; const float* W; const float* bias; float* C;
    if (sel == 0)      { A = q; W = wq; bias = bq; C = gQ; }
    else if (sel == 1) { A = k; W = wk; bias = bk; C = gK; }
    else               { A = v; W = wv; bias = bv; C = gV; }

    gemm_body(A, W, bias, C, B_ * S_, DM, DM, bm, bn, As, Ws);
}

__global__ __launch_bounds__(256, 2) void gemm_nt_bias(
    const float* __restrict__ A, const float* __restrict__ W,
    const float* __restrict__ bias, float* __restrict__ C,
    int M, int N, int K)
{
    __shared__ float As[2][8][128];
    __shared__ float Ws[2][8][128];
    gemm_body(A, W, bias, C, M, N, K,
              blockIdx.y * 128, blockIdx.x * 128, As, Ws);
}

// ---------------------------------------------------------------------------
// Causal flash attention v6: R3 inner loops (proven 610us) but q staged in
// SHARED memory (padded stride 68 floats -> conflict-free LDS.128) instead
// of 64 registers. Dynamic smem 66KB/CTA; __launch_bounds__(128,3) -> 3
// CTAs/SM (12 warps) vs 2 before.
// ---------------------------------------------------------------------------
#define QS_STRIDE 68
#define ATTN_SMEM ((64 * 64 * 2 + 128 * QS_STRIDE) * 4)

template<bool MASKED>
__device__ __forceinline__ void process16(
    uint32_t ksC, uint32_t vsC,
    uint32_t qsAddr,                      // this thread's q row in smem
    u64* __restrict__ o2,
    float& m, float& l, int rel_end)
{
    u64 s2[16];
#pragma unroll
    for (int j = 0; j < 16; j++) s2[j] = 0ull;

    // Scores: d4-outer (q from smem, conflict-free), j-inner -> 16 chains.
#pragma unroll
    for (int d4 = 0; d4 < 16; d4++) {
        u64 qa, qb;
        LDS_V2B64(qa, qb, qsAddr + d4 * 16);
#pragma unroll
        for (int j = 0; j < 16; j++) {
            u64 ka, kb;
            LDS_V2B64(ka, kb, ksC + j * 256 + d4 * 16);
            FMA2(s2[j], qa, ka, s2[j]);
            FMA2(s2[j], qb, kb, s2[j]);
        }
    }

    float s[16];
    float cmax = -1e30f;
#pragma unroll
    for (int j = 0; j < 16; j++) {
        float lo, hi;
        UNPACK2(lo, hi, s2[j]);
        float sj = (lo + hi) * 0.125f;            // 1/sqrt(64)
        if (MASKED) { if (j >= rel_end) sj = -1e30f; }
        s[j] = sj;
        cmax = fmaxf(cmax, sj);
    }

    const float newm = fmaxf(m, cmax);
    const float corr = __expf(m - newm);          // 0 on first chunk
    m = newm;
    l *= corr;
    u64 corr2; PACK2(corr2, corr, corr);
#pragma unroll
    for (int d = 0; d < 32; d++) MUL2(o2[d], o2[d], corr2);

    float lsum = 0.f;
#pragma unroll
    for (int j = 0; j < 16; j++) {
        s[j] = __expf(s[j] - newm);               // masked -> 0
        lsum += s[j];
    }
    l += lsum;

    // PV: j-outer, d-inner.
#pragma unroll
    for (int j = 0; j < 16; j++) {
        u64 p2; PACK2(p2, s[j], s[j]);
#pragma unroll
        for (int d = 0; d < 16; d++) {
            u64 va, vb;
            LDS_V2B64(va, vb, vsC + j * 256 + d * 16);
            FMA2(o2[2 * d],     p2, va, o2[2 * d]);
            FMA2(o2[2 * d + 1], p2, vb, o2[2 * d + 1]);
        }
    }
}

__global__ __launch_bounds__(128, 3) void attn_kernel(
    const float* __restrict__ Q, const float* __restrict__ K,
    const float* __restrict__ V, float* __restrict__ X)
{
    extern __shared__ float sm[];
    float* Ks = sm;                 // 64*64 floats
    float* Vs = sm + 64 * 64;       // 64*64 floats
    float* Qs = sm + 2 * 64 * 64;   // 128*68 floats (padded rows)

    const int tid = threadIdx.x;
    const int h   = blockIdx.y;
    const int b   = blockIdx.z;
    const int qblk = (int)gridDim.x - 1 - (int)blockIdx.x;   // LPT order
    const int q0   = qblk * 128;
    const int qi   = q0 + tid;

    const uint32_t ksBase = (uint32_t)__cvta_generic_to_shared(Ks);
    const uint32_t vsBase = (uint32_t)__cvta_generic_to_shared(Vs);
    const uint32_t qsAddr = (uint32_t)__cvta_generic_to_shared(Qs)
                          + tid * (QS_STRIDE * 4);

    // Stage this thread's q row into padded smem (write pattern ==
    // read pattern; conflict-free per 8-lane phase).
    {
        const float4* qp = (const float4*)(Q + ((size_t)(b * S_ + qi)) * DM + h * DK);
        float4* qs4 = (float4*)(Qs + tid * QS_STRIDE);
#pragma unroll
        for (int i = 0; i < 16; i++) qs4[i] = qp[i];
    }

    u64 o2[32];
#pragma unroll
    for (int d = 0; d < 32; d++) o2[d] = 0ull;
    float m = -1e30f, l = 0.f;

    const int kmax = q0 + 128;

    for (int c0 = 0; c0 < kmax; c0 += 64) {
        const float4* kb4 = (const float4*)(K + ((size_t)(b * S_ + c0)) * DM + h * DK);
        const float4* vb4 = (const float4*)(V + ((size_t)(b * S_ + c0)) * DM + h * DK);
#pragma unroll
        for (int i = 0; i < 8; i++) {
            const int idx = tid + i * 128;        // 0..1023
            const int j   = idx >> 4;
            const int cc  = idx & 15;
            ((float4*)Ks)[idx] = kb4[(size_t)j * (DM / 4) + cc];
            ((float4*)Vs)[idx] = vb4[(size_t)j * (DM / 4) + cc];
        }
        __syncthreads();

        int jend = qi - c0 + 1;
        if (jend > 64) jend = 64;

        int jb = 0;
        for (; jb + 16 <= jend; jb += 16)
            process16<false>(ksBase + jb * 256, vsBase + jb * 256,
                             qsAddr, o2, m, l, 16);
        const int rem = jend - jb;
        if (rem > 0)
            process16<true>(ksBase + jb * 256, vsBase + jb * 256,
                            qsAddr, o2, m, l, rem);
        __syncthreads();
    }

    const float inv = 1.f / l;
    float* xptr = X + ((size_t)(b * S_ + qi)) * DM + h * DK;
#pragma unroll
    for (int d = 0; d < 16; d++) {
        float a0, a1, a2, a3;
        UNPACK2(a0, a1, o2[2 * d]);
        UNPACK2(a2, a3, o2[2 * d + 1]);
        float4 ov = { a0 * inv, a1 * inv, a2 * inv, a3 * inv };
        *(float4*)(xptr + d * 4) = ov;
    }
}

// ---------------------------------------------------------------------------
// Launch
// Inputs: 0:q 1:k 2:v 3:mask 4:wq 5:bq 6:wk 7:bk 8:wv 9:bv 10:wo 11:bo
// ---------------------------------------------------------------------------
extern "C" void kernel_launch(void* const* d_in, const int* in_sizes, int n_in,
                              void* d_out, int out_size)
{
    const float* q  = (const float*)d_in[0];
    const float* k  = (const float*)d_in[1];
    const float* v  = (const float*)d_in[2];
    const float* wq = (const float*)d_in[4];
    const float* bq = (const float*)d_in[5];
    const float* wk = (const float*)d_in[6];
    const float* bk = (const float*)d_in[7];
    const float* wv = (const float*)d_in[8];
    const float* bv = (const float*)d_in[9];
    const float* wo = (const float*)d_in[10];
    const float* bo = (const float*)d_in[11];
    float* out = (float*)d_out;

    float *gQ, *gK, *gV, *gX;
    cudaGetSymbolAddress((void**)&gQ, g_Q);
    cudaGetSymbolAddress((void**)&gK, g_K);
    cudaGetSymbolAddress((void**)&gV, g_V);
    cudaGetSymbolAddress((void**)&gX, g_X);

    static int smem_set = 0;
    if (!smem_set) {
        cudaFuncSetAttribute(attn_kernel,
                             cudaFuncAttributeMaxDynamicSharedMemorySize,
                             ATTN_SMEM);
        smem_set = 1;
    }

    const int M = B_ * S_;  // 4096

    dim3 qkvgrid(18, M / 128);       // (18, 32) fused QKV
    gemm_qkv<<<qkvgrid, 256>>>(q, k, v, wq, bq, wk, bk, wv, bv, gQ, gK, gV);

    dim3 agrid(S_ / 128, H_, B_);    // (16, 12, 2)
    attn_kernel<<<agrid, 128, ATTN_SMEM>>>(gQ, gK, gV, gX);

    dim3 ggrid(DM / 128, M / 128);   // (6, 32)
    gemm_nt_bias<<<ggrid, 256>>>(gX, wo, bo, out, M, DM, DM);
}

// round 11
// speedup vs baseline: 1.6329x; 1.2066x over previous
#include <cuda_runtime.h>
#include <cstdint>

// Problem constants
#define B_  2
#define S_  2048
#define DM  768
#define H_  12
#define DK  64

// Scratch (allocation-free rule: device globals)
__device__ float g_Q[B_ * S_ * DM];
__device__ float g_K[B_ * S_ * DM];
__device__ float g_V[B_ * S_ * DM];
__device__ float g_X[B_ * S_ * DM];

typedef unsigned long long u64;

// ---------------------------------------------------------------------------
// fp32x2 helpers (attention)
// ---------------------------------------------------------------------------
#define FMA2(d, a, b, c) \
    asm("fma.rn.f32x2 %0, %1, %2, %3;" : "=l"(d) : "l"(a), "l"(b), "l"(c))
#define MUL2(d, a, b) \
    asm("mul.rn.f32x2 %0, %1, %2;" : "=l"(d) : "l"(a), "l"(b))
#define PACK2(d, lo, hi) \
    asm("mov.b64 %0, {%1, %2};" : "=l"(d) : "f"(lo), "f"(hi))
#define UNPACK2(lo, hi, s) \
    asm("mov.b64 {%0, %1}, %2;" : "=f"(lo), "=f"(hi) : "l"(s))
#define LDS_V2B64(d0, d1, addr) \
    asm volatile("ld.shared.v2.b64 {%0, %1}, [%2];" \
                 : "=l"(d0), "=l"(d1) : "r"(addr))

// ---------------------------------------------------------------------------
// TF32 tensor-core helpers
// ---------------------------------------------------------------------------
__device__ __forceinline__ uint32_t f2tf32(float x) {
    uint32_t r;
    asm("cvt.rna.tf32.f32 %0, %1;" : "=r"(r) : "f"(x));
    return r;
}

__device__ __forceinline__ void split_tf32(float x, uint32_t& hi, uint32_t& lo) {
    hi = f2tf32(x);
    lo = f2tf32(x - __uint_as_float(hi));
}

__device__ __forceinline__ void mma_tf32(float* c, const uint32_t* a,
                                         const uint32_t* b) {
    asm volatile(
        "mma.sync.aligned.m16n8k8.row.col.f32.tf32.tf32.f32 "
        "{%0,%1,%2,%3}, {%4,%5,%6,%7}, {%8,%9}, {%0,%1,%2,%3};"
        : "+f"(c[0]), "+f"(c[1]), "+f"(c[2]), "+f"(c[3])
        : "r"(a[0]), "r"(a[1]), "r"(a[2]), "r"(a[3]),
          "r"(b[0]), "r"(b[1]));
}

// ---------------------------------------------------------------------------
// Tensor-core GEMM: C[M,N] = A[M,K] @ W[N,K]^T + bias[N], 3xTF32 precision.
// 64x64 CTA tile, 128 threads (4 warps, 2x2), warp tile 32x32,
// BK=16 double-buffered. W rows ARE the col-major B operand (no transpose).
// Smem rows padded to 20 floats -> conflict-free fragment loads.
// ---------------------------------------------------------------------------
#define TCBM 64
#define TCBK 16
#define TCPAD 20

__device__ __forceinline__ void gemm_tc_body(
    const float* __restrict__ A, const float* __restrict__ W,
    const float* __restrict__ bias, float* __restrict__ C,
    int N, int K, int bm, int bn,
    float (*As)[TCBM * TCPAD], float (*Ws)[TCBM * TCPAD])
{
    const int t    = threadIdx.x;
    const int lane = t & 31;
    const int wid  = t >> 5;
    const int wm   = (wid >> 1) * 32;   // warp M offset in CTA tile
    const int wn   = (wid & 1) * 32;    // warp N offset
    const int g    = lane >> 2;         // fragment group (0..7)
    const int tg   = lane & 3;          // thread-in-group (0..3)

    // Staging: thread covers rows r0 and r0+32, one float4 each at col cs.
    const int r0 = t >> 2;
    const int cs = (t & 3) * 4;

    const float* Ap = A + (size_t)(bm + r0) * K + cs;
    const float* Wp = W + (size_t)(bn + r0) * K + cs;
    const size_t rowskip = (size_t)32 * K;

    float acc[2][4][4];
#pragma unroll
    for (int i = 0; i < 2; i++)
#pragma unroll
        for (int j = 0; j < 4; j++)
#pragma unroll
            for (int c = 0; c < 4; c++) acc[i][j][c] = 0.f;

    // stage buffer 0
    {
        float4 a0 = *(const float4*)(Ap);
        float4 a1 = *(const float4*)(Ap + rowskip);
        float4 w0 = *(const float4*)(Wp);
        float4 w1 = *(const float4*)(Wp + rowskip);
        *(float4*)&As[0][r0 * TCPAD + cs]        = a0;
        *(float4*)&As[0][(r0 + 32) * TCPAD + cs] = a1;
        *(float4*)&Ws[0][r0 * TCPAD + cs]        = w0;
        *(float4*)&Ws[0][(r0 + 32) * TCPAD + cs] = w1;
    }
    __syncthreads();

    int cur = 0;
    for (int kt = 0; kt < K; kt += TCBK) {
        const bool has_next = (kt + TCBK) < K;
        float4 a0n, a1n, w0n, w1n;
        if (has_next) {
            a0n = *(const float4*)(Ap + kt + TCBK);
            a1n = *(const float4*)(Ap + rowskip + kt + TCBK);
            w0n = *(const float4*)(Wp + kt + TCBK);
            w1n = *(const float4*)(Wp + rowskip + kt + TCBK);
        }

        const float* as = As[cur];
        const float* ws = Ws[cur];
#pragma unroll
        for (int k0 = 0; k0 < TCBK; k0 += 8) {
            // A fragments (two m16k8 tiles), split hi/lo.
            uint32_t ah[2][4], al[2][4];
#pragma unroll
            for (int mt = 0; mt < 2; mt++) {
                const int row = wm + mt * 16 + g;
                float x0 = as[row * TCPAD + k0 + tg];
                float x1 = as[(row + 8) * TCPAD + k0 + tg];
                float x2 = as[row * TCPAD + k0 + tg + 4];
                float x3 = as[(row + 8) * TCPAD + k0 + tg + 4];
                split_tf32(x0, ah[mt][0], al[mt][0]);
                split_tf32(x1, ah[mt][1], al[mt][1]);
                split_tf32(x2, ah[mt][2], al[mt][2]);
                split_tf32(x3, ah[mt][3], al[mt][3]);
            }
            // B fragments (four n8k8 tiles) from W rows, split hi/lo.
            uint32_t bh[4][2], bl[4][2];
#pragma unroll
            for (int nt = 0; nt < 4; nt++) {
                const int n = wn + nt * 8 + g;
                float y0 = ws[n * TCPAD + k0 + tg];
                float y1 = ws[n * TCPAD + k0 + tg + 4];
                split_tf32(y0, bh[nt][0], bl[nt][0]);
                split_tf32(y1, bh[nt][1], bl[nt][1]);
            }
            // 3xTF32: hi*hi + lo*hi + hi*lo
#pragma unroll
            for (int mt = 0; mt < 2; mt++)
#pragma unroll
                for (int nt = 0; nt < 4; nt++) {
                    mma_tf32(acc[mt][nt], ah[mt], bh[nt]);
                    mma_tf32(acc[mt][nt], al[mt], bh[nt]);
                    mma_tf32(acc[mt][nt], ah[mt], bl[nt]);
                }
        }

        if (has_next) {
            const int nxt = cur ^ 1;
            *(float4*)&As[nxt][r0 * TCPAD + cs]        = a0n;
            *(float4*)&As[nxt][(r0 + 32) * TCPAD + cs] = a1n;
            *(float4*)&Ws[nxt][r0 * TCPAD + cs]        = w0n;
            *(float4*)&Ws[nxt][(r0 + 32) * TCPAD + cs] = w1n;
        }
        __syncthreads();
        cur ^= 1;
    }

    // Epilogue: bias + store (c0,c1 are adjacent cols -> float2 stores).
#pragma unroll
    for (int mt = 0; mt < 2; mt++) {
        const int row = bm + wm + mt * 16 + g;
#pragma unroll
        for (int nt = 0; nt < 4; nt++) {
            const int col = bn + wn + nt * 8 + tg * 2;
            const float b0 = bias[col], b1 = bias[col + 1];
            float2 v0 = { acc[mt][nt][0] + b0, acc[mt][nt][1] + b1 };
            float2 v1 = { acc[mt][nt][2] + b0, acc[mt][nt][3] + b1 };
            *(float2*)&C[(size_t)row * N + col]       = v0;
            *(float2*)&C[(size_t)(row + 8) * N + col] = v1;
        }
    }
}

// Fused QKV: blockIdx.x in [0,36): [0,12)->Q, [12,24)->K, [24,36)->V.
__global__ __launch_bounds__(128) void gemm_qkv_tc(
    const float* __restrict__ q, const float* __restrict__ k,
    const float* __restrict__ v,
    const float* __restrict__ wq, const float* __restrict__ bq,
    const float* __restrict__ wk, const float* __restrict__ bk,
    const float* __restrict__ wv, const float* __restrict__ bv,
    float* __restrict__ gQ, float* __restrict__ gK, float* __restrict__ gV)
{
    __shared__ float As[2][TCBM * TCPAD];
    __shared__ float Ws[2][TCBM * TCPAD];

    const int bx  = blockIdx.x;
    const int sel = bx / 12;
    const int bn  = (bx % 12) * 64;
    const int bm  = blockIdx.y * 64;

    const float* A; const float* W; const float* bias; float* C;
    if (sel == 0)      { A = q; W = wq; bias = bq; C = gQ; }
    else if (sel == 1) { A = k; W = wk; bias = bk; C = gK; }
    else               { A = v; W = wv; bias = bv; C = gV; }

    gemm_tc_body(A, W, bias, C, DM, DM, bm, bn, As, Ws);
}

__global__ __launch_bounds__(128) void gemm_wo_tc(
    const float* __restrict__ A, const float* __restrict__ W,
    const float* __restrict__ bias, float* __restrict__ C)
{
    __shared__ float As[2][TCBM * TCPAD];
    __shared__ float Ws[2][TCBM * TCPAD];
    gemm_tc_body(A, W, bias, C, DM, DM,
                 blockIdx.y * 64, blockIdx.x * 64, As, Ws);
}

// ---------------------------------------------------------------------------
// Causal flash attention (R3/R4 proven version, 610us):
// 1 thread/query, 128 queries/block, fp32x2 packed math, 16-key chunks.
// ---------------------------------------------------------------------------
template<bool MASKED>
__device__ __forceinline__ void process16(
    uint32_t ksC, uint32_t vsC,
    const u64* __restrict__ q2, u64* __restrict__ o2,
    float& m, float& l, int rel_end)
{
    u64 s2[16];
#pragma unroll
    for (int j = 0; j < 16; j++) s2[j] = 0ull;

#pragma unroll
    for (int d = 0; d < 16; d++) {
        const u64 qa = q2[2 * d], qb = q2[2 * d + 1];
#pragma unroll
        for (int j = 0; j < 16; j++) {
            u64 ka, kb;
            LDS_V2B64(ka, kb, ksC + j * 256 + d * 16);
            FMA2(s2[j], qa, ka, s2[j]);
            FMA2(s2[j], qb, kb, s2[j]);
        }
    }

    float s[16];
    float cmax = -1e30f;
#pragma unroll
    for (int j = 0; j < 16; j++) {
        float lo, hi;
        UNPACK2(lo, hi, s2[j]);
        float sj = (lo + hi) * 0.125f;            // 1/sqrt(64)
        if (MASKED) { if (j >= rel_end) sj = -1e30f; }
        s[j] = sj;
        cmax = fmaxf(cmax, sj);
    }

    const float newm = fmaxf(m, cmax);
    const float corr = __expf(m - newm);          // 0 on first chunk
    m = newm;
    l *= corr;
    u64 corr2; PACK2(corr2, corr, corr);
#pragma unroll
    for (int d = 0; d < 32; d++) MUL2(o2[d], o2[d], corr2);

    float lsum = 0.f;
#pragma unroll
    for (int j = 0; j < 16; j++) {
        s[j] = __expf(s[j] - newm);               // masked -> 0
        lsum += s[j];
    }
    l += lsum;

#pragma unroll
    for (int j = 0; j < 16; j++) {
        u64 p2; PACK2(p2, s[j], s[j]);
#pragma unroll
        for (int d = 0; d < 16; d++) {
            u64 va, vb;
            LDS_V2B64(va, vb, vsC + j * 256 + d * 16);
            FMA2(o2[2 * d],     p2, va, o2[2 * d]);
            FMA2(o2[2 * d + 1], p2, vb, o2[2 * d + 1]);
        }
    }
}

__global__ __launch_bounds__(128) void attn_kernel(
    const float* __restrict__ Q, const float* __restrict__ K,
    const float* __restrict__ V, float* __restrict__ X)
{
    __shared__ float Ks[64 * 64];
    __shared__ float Vs[64 * 64];

    const int tid = threadIdx.x;
    const int h   = blockIdx.y;
    const int b   = blockIdx.z;
    const int qblk = (int)gridDim.x - 1 - (int)blockIdx.x;   // LPT order
    const int q0   = qblk * 128;
    const int qi   = q0 + tid;

    const uint32_t ksBase = (uint32_t)__cvta_generic_to_shared(Ks);
    const uint32_t vsBase = (uint32_t)__cvta_generic_to_shared(Vs);

    u64 q2[32];
    {
        const float4* qptr = (const float4*)(Q + ((size_t)(b * S_ + qi)) * DM + h * DK);
#pragma unroll
        for (int d4 = 0; d4 < 16; d4++) {
            float4 qv = qptr[d4];
            PACK2(q2[2 * d4],     qv.x, qv.y);
            PACK2(q2[2 * d4 + 1], qv.z, qv.w);
        }
    }

    u64 o2[32];
#pragma unroll
    for (int d = 0; d < 32; d++) o2[d] = 0ull;
    float m = -1e30f, l = 0.f;

    const int kmax = q0 + 128;

    for (int c0 = 0; c0 < kmax; c0 += 64) {
        const float4* kb4 = (const float4*)(K + ((size_t)(b * S_ + c0)) * DM + h * DK);
        const float4* vb4 = (const float4*)(V + ((size_t)(b * S_ + c0)) * DM + h * DK);
#pragma unroll
        for (int i = 0; i < 8; i++) {
            const int idx = tid + i * 128;        // 0..1023
            const int j   = idx >> 4;
            const int cc  = idx & 15;
            ((float4*)Ks)[idx] = kb4[(size_t)j * (DM / 4) + cc];
            ((float4*)Vs)[idx] = vb4[(size_t)j * (DM / 4) + cc];
        }
        __syncthreads();

        int jend = qi - c0 + 1;
        if (jend > 64) jend = 64;

        int jb = 0;
        for (; jb + 16 <= jend; jb += 16)
            process16<false>(ksBase + jb * 256, vsBase + jb * 256,
                             q2, o2, m, l, 16);
        const int rem = jend - jb;
        if (rem > 0)
            process16<true>(ksBase + jb * 256, vsBase + jb * 256,
                            q2, o2, m, l, rem);
        __syncthreads();
    }

    const float inv = 1.f / l;
    float* xptr = X + ((size_t)(b * S_ + qi)) * DM + h * DK;
#pragma unroll
    for (int d = 0; d < 16; d++) {
        float a0, a1, a2, a3;
        UNPACK2(a0, a1, o2[2 * d]);
        UNPACK2(a2, a3, o2[2 * d + 1]);
        float4 ov = { a0 * inv, a1 * inv, a2 * inv, a3 * inv };
        *(float4*)(xptr + d * 4) = ov;
    }
}

// ---------------------------------------------------------------------------
// Launch
// Inputs: 0:q 1:k 2:v 3:mask 4:wq 5:bq 6:wk 7:bk 8:wv 9:bv 10:wo 11:bo
// ---------------------------------------------------------------------------
extern "C" void kernel_launch(void* const* d_in, const int* in_sizes, int n_in,
                              void* d_out, int out_size)
{
    const float* q  = (const float*)d_in[0];
    const float* k  = (const float*)d_in[1];
    const float* v  = (const float*)d_in[2];
    const float* wq = (const float*)d_in[4];
    const float* bq = (const float*)d_in[5];
    const float* wk = (const float*)d_in[6];
    const float* bk = (const float*)d_in[7];
    const float* wv = (const float*)d_in[8];
    const float* bv = (const float*)d_in[9];
    const float* wo = (const float*)d_in[10];
    const float* bo = (const float*)d_in[11];
    float* out = (float*)d_out;

    float *gQ, *gK, *gV, *gX;
    cudaGetSymbolAddress((void**)&gQ, g_Q);
    cudaGetSymbolAddress((void**)&gK, g_K);
    cudaGetSymbolAddress((void**)&gV, g_V);
    cudaGetSymbolAddress((void**)&gX, g_X);

    const int M = B_ * S_;  // 4096

    dim3 qkvgrid(36, M / 64);        // (36, 64): 3 x 12 n-tiles, 64 m-tiles
    gemm_qkv_tc<<<qkvgrid, 128>>>(q, k, v, wq, bq, wk, bk, wv, bv, gQ, gK, gV);

    dim3 agrid(S_ / 128, H_, B_);    // (16, 12, 2)
    attn_kernel<<<agrid, 128>>>(gQ, gK, gV, gX);

    dim3 wogrid(DM / 64, M / 64);    // (12, 64)
    gemm_wo_tc<<<wogrid, 128>>>(gX, wo, bo, out);
}

// round 14
// speedup vs baseline: 1.9189x; 1.1751x over previous
#include <cuda_runtime.h>
#include <cstdint>

// Problem constants
#define B_  2
#define S_  2048
#define DM  768
#define H_  12
#define DK  64

// Scratch (allocation-free rule: device globals)
__device__ float g_Q[B_ * S_ * DM];
__device__ float g_K[B_ * S_ * DM];
__device__ float g_V[B_ * S_ * DM];
__device__ float g_X[B_ * S_ * DM];

// ---------------------------------------------------------------------------
// TF32 tensor-core helpers (verified in R9)
// ---------------------------------------------------------------------------
__device__ __forceinline__ uint32_t f2tf32(float x) {
    uint32_t r;
    asm("cvt.rna.tf32.f32 %0, %1;" : "=r"(r) : "f"(x));
    return r;
}

__device__ __forceinline__ void split_tf32(float x, uint32_t& hi, uint32_t& lo) {
    hi = f2tf32(x);
    lo = f2tf32(x - __uint_as_float(hi));
}

__device__ __forceinline__ void mma_tf32(float* c, const uint32_t* a,
                                         const uint32_t* b) {
    asm volatile(
        "mma.sync.aligned.m16n8k8.row.col.f32.tf32.tf32.f32 "
        "{%0,%1,%2,%3}, {%4,%5,%6,%7}, {%8,%9}, {%0,%1,%2,%3};"
        : "+f"(c[0]), "+f"(c[1]), "+f"(c[2]), "+f"(c[3])
        : "r"(a[0]), "r"(a[1]), "r"(a[2]), "r"(a[3]),
          "r"(b[0]), "r"(b[1]));
}

// ---------------------------------------------------------------------------
// Tensor-core GEMM (verified R9): C[M,N] = A[M,K] @ W[N,K]^T + bias[N]
// ---------------------------------------------------------------------------
#define TCBM 64
#define TCBK 16
#define TCPAD 20

__device__ __forceinline__ void gemm_tc_body(
    const float* __restrict__ A, const float* __restrict__ W,
    const float* __restrict__ bias, float* __restrict__ C,
    int N, int K, int bm, int bn,
    float (*As)[TCBM * TCPAD], float (*Ws)[TCBM * TCPAD])
{
    const int t    = threadIdx.x;
    const int lane = t & 31;
    const int wid  = t >> 5;
    const int wm   = (wid >> 1) * 32;
    const int wn   = (wid & 1) * 32;
    const int g    = lane >> 2;
    const int tg   = lane & 3;

    const int r0 = t >> 2;
    const int cs = (t & 3) * 4;

    const float* Ap = A + (size_t)(bm + r0) * K + cs;
    const float* Wp = W + (size_t)(bn + r0) * K + cs;
    const size_t rowskip = (size_t)32 * K;

    float acc[2][4][4];
#pragma unroll
    for (int i = 0; i < 2; i++)
#pragma unroll
        for (int j = 0; j < 4; j++)
#pragma unroll
            for (int c = 0; c < 4; c++) acc[i][j][c] = 0.f;

    {
        float4 a0 = *(const float4*)(Ap);
        float4 a1 = *(const float4*)(Ap + rowskip);
        float4 w0 = *(const float4*)(Wp);
        float4 w1 = *(const float4*)(Wp + rowskip);
        *(float4*)&As[0][r0 * TCPAD + cs]        = a0;
        *(float4*)&As[0][(r0 + 32) * TCPAD + cs] = a1;
        *(float4*)&Ws[0][r0 * TCPAD + cs]        = w0;
        *(float4*)&Ws[0][(r0 + 32) * TCPAD + cs] = w1;
    }
    __syncthreads();

    int cur = 0;
    for (int kt = 0; kt < K; kt += TCBK) {
        const bool has_next = (kt + TCBK) < K;
        float4 a0n, a1n, w0n, w1n;
        if (has_next) {
            a0n = *(const float4*)(Ap + kt + TCBK);
            a1n = *(const float4*)(Ap + rowskip + kt + TCBK);
            w0n = *(const float4*)(Wp + kt + TCBK);
            w1n = *(const float4*)(Wp + rowskip + kt + TCBK);
        }

        const float* as = As[cur];
        const float* ws = Ws[cur];
#pragma unroll
        for (int k0 = 0; k0 < TCBK; k0 += 8) {
            uint32_t ah[2][4], al[2][4];
#pragma unroll
            for (int mt = 0; mt < 2; mt++) {
                const int row = wm + mt * 16 + g;
                split_tf32(as[row * TCPAD + k0 + tg],           ah[mt][0], al[mt][0]);
                split_tf32(as[(row + 8) * TCPAD + k0 + tg],     ah[mt][1], al[mt][1]);
                split_tf32(as[row * TCPAD + k0 + tg + 4],       ah[mt][2], al[mt][2]);
                split_tf32(as[(row + 8) * TCPAD + k0 + tg + 4], ah[mt][3], al[mt][3]);
            }
            uint32_t bh[4][2], bl[4][2];
#pragma unroll
            for (int nt = 0; nt < 4; nt++) {
                const int n = wn + nt * 8 + g;
                split_tf32(ws[n * TCPAD + k0 + tg],     bh[nt][0], bl[nt][0]);
                split_tf32(ws[n * TCPAD + k0 + tg + 4], bh[nt][1], bl[nt][1]);
            }
#pragma unroll
            for (int mt = 0; mt < 2; mt++)
#pragma unroll
                for (int nt = 0; nt < 4; nt++) {
                    mma_tf32(acc[mt][nt], ah[mt], bh[nt]);
                    mma_tf32(acc[mt][nt], al[mt], bh[nt]);
                    mma_tf32(acc[mt][nt], ah[mt], bl[nt]);
                }
        }

        if (has_next) {
            const int nxt = cur ^ 1;
            *(float4*)&As[nxt][r0 * TCPAD + cs]        = a0n;
            *(float4*)&As[nxt][(r0 + 32) * TCPAD + cs] = a1n;
            *(float4*)&Ws[nxt][r0 * TCPAD + cs]        = w0n;
            *(float4*)&Ws[nxt][(r0 + 32) * TCPAD + cs] = w1n;
        }
        __syncthreads();
        cur ^= 1;
    }

#pragma unroll
    for (int mt = 0; mt < 2; mt++) {
        const int row = bm + wm + mt * 16 + g;
#pragma unroll
        for (int nt = 0; nt < 4; nt++) {
            const int col = bn + wn + nt * 8 + tg * 2;
            const float b0 = bias[col], b1 = bias[col + 1];
            float2 v0 = { acc[mt][nt][0] + b0, acc[mt][nt][1] + b1 };
            float2 v1 = { acc[mt][nt][2] + b0, acc[mt][nt][3] + b1 };
            *(float2*)&C[(size_t)row * N + col]       = v0;
            *(float2*)&C[(size_t)(row + 8) * N + col] = v1;
        }
    }
}

__global__ __launch_bounds__(128) void gemm_qkv_tc(
    const float* __restrict__ q, const float* __restrict__ k,
    const float* __restrict__ v,
    const float* __restrict__ wq, const float* __restrict__ bq,
    const float* __restrict__ wk, const float* __restrict__ bk,
    const float* __restrict__ wv, const float* __restrict__ bv,
    float* __restrict__ gQ, float* __restrict__ gK, float* __restrict__ gV)
{
    __shared__ float As[2][TCBM * TCPAD];
    __shared__ float Ws[2][TCBM * TCPAD];

    const int bx  = blockIdx.x;
    const int sel = bx / 12;
    const int bn  = (bx % 12) * 64;
    const int bm  = blockIdx.y * 64;

    const float* A; const float* W; const float* bias; float* C;
    if (sel == 0)      { A = q; W = wq; bias = bq; C = gQ; }
    else if (sel == 1) { A = k; W = wk; bias = bk; C = gK; }
    else               { A = v; W = wv; bias = bv; C = gV; }

    gemm_tc_body(A, W, bias, C, DM, DM, bm, bn, As, Ws);
}

__global__ __launch_bounds__(128) void gemm_wo_tc(
    const float* __restrict__ A, const float* __restrict__ W,
    const float* __restrict__ bias, float* __restrict__ C)
{
    __shared__ float As[2][TCBM * TCPAD];
    __shared__ float Ws[2][TCBM * TCPAD];
    gemm_tc_body(A, W, bias, C, DM, DM,
                 blockIdx.y * 64, blockIdx.x * 64, As, Ws);
}

// ---------------------------------------------------------------------------
// Tensor-core causal flash attention.
// CTA: 64 queries x (b,h); 4 warps x m16 query rows; 64-key tiles.
// K/V staged ONCE per tile as pre-split tf32 hi/lo (uint32) smem tiles.
// S = Q K^T (3xTF32), fragment-layout online softmax, P via warp-private
// smem relayout, O += P V (3xTF32, V read from natural [key][dim] tile).
// ---------------------------------------------------------------------------
#define AST 68   // smem row stride (floats/uints)
#define ATTN_TC_SMEM ((4 * 64 * AST + 4 * 16 * AST) * 4)

__global__ __launch_bounds__(128) void attn_tc(
    const float* __restrict__ Q, const float* __restrict__ K,
    const float* __restrict__ V, float* __restrict__ X)
{
    extern __shared__ uint32_t sm[];
    uint32_t* Khi = sm;
    uint32_t* Klo = sm + 64 * AST;
    uint32_t* Vhi = sm + 2 * 64 * AST;
    uint32_t* Vlo = sm + 3 * 64 * AST;
    float*    Ps  = (float*)(sm + 4 * 64 * AST);   // [4 warps][16*AST]

    const int tid  = threadIdx.x;
    const int lane = tid & 31;
    const int wid  = tid >> 5;
    const int g    = lane >> 2;
    const int tg   = lane & 3;
    const int wm   = wid * 16;
    const int h    = blockIdx.y;
    const int b    = blockIdx.z;
    const int qblk = (int)gridDim.x - 1 - (int)blockIdx.x;   // LPT order
    const int q0   = qblk * 64;
    const int qi0  = q0 + wm + g;
    const int qi1  = qi0 + 8;
    float* psw = Ps + wid * (16 * AST);

    // Preconvert this thread's Q fragments (hi/lo), reused across all tiles.
    uint32_t qh[8][4], ql[8][4];
    {
        const float* Q0 = Q + ((size_t)(b * S_ + qi0)) * DM + h * DK;
        const float* Q1 = Q0 + 8 * DM;
#pragma unroll
        for (int kk = 0; kk < 8; kk++) {
            split_tf32(Q0[kk * 8 + tg],     qh[kk][0], ql[kk][0]);
            split_tf32(Q1[kk * 8 + tg],     qh[kk][1], ql[kk][1]);
            split_tf32(Q0[kk * 8 + tg + 4], qh[kk][2], ql[kk][2]);
            split_tf32(Q1[kk * 8 + tg + 4], qh[kk][3], ql[kk][3]);
        }
    }

    float o[8][4];
#pragma unroll
    for (int nt = 0; nt < 8; nt++)
#pragma unroll
        for (int c = 0; c < 4; c++) o[nt][c] = 0.f;
    float m0 = -1e30f, m1 = -1e30f, l0 = 0.f, l1 = 0.f;

    for (int c0 = 0; c0 < q0 + 64; c0 += 64) {
        // Stage K/V tile, converting to tf32 hi/lo once for the whole CTA.
        const float4* kb4 = (const float4*)(K + ((size_t)(b * S_ + c0)) * DM + h * DK);
        const float4* vb4 = (const float4*)(V + ((size_t)(b * S_ + c0)) * DM + h * DK);
#pragma unroll
        for (int i = 0; i < 8; i++) {
            const int idx = tid + i * 128;        // 0..1023
            const int j   = idx >> 4;             // key row
            const int c4  = idx & 15;             // dim float4 index
            float4 kv = kb4[(size_t)j * (DM / 4) + c4];
            float4 vv = vb4[(size_t)j * (DM / 4) + c4];
            const int base = j * AST + c4 * 4;
            uint32_t hi, lo;
            split_tf32(kv.x, hi, lo); Khi[base + 0] = hi; Klo[base + 0] = lo;
            split_tf32(kv.y, hi, lo); Khi[base + 1] = hi; Klo[base + 1] = lo;
            split_tf32(kv.z, hi, lo); Khi[base + 2] = hi; Klo[base + 2] = lo;
            split_tf32(kv.w, hi, lo); Khi[base + 3] = hi; Klo[base + 3] = lo;
            split_tf32(vv.x, hi, lo); Vhi[base + 0] = hi; Vlo[base + 0] = lo;
            split_tf32(vv.y, hi, lo); Vhi[base + 1] = hi; Vlo[base + 1] = lo;
            split_tf32(vv.z, hi, lo); Vhi[base + 2] = hi; Vlo[base + 2] = lo;
            split_tf32(vv.w, hi, lo); Vhi[base + 3] = hi; Vlo[base + 3] = lo;
        }
        __syncthreads();

        if (c0 < q0 + wm + 16) {     // tile intersects this warp's rows
            // ----- S = Q K^T (3xTF32) -----
            float s[8][4];
#pragma unroll
            for (int nt = 0; nt < 8; nt++)
#pragma unroll
                for (int c = 0; c < 4; c++) s[nt][c] = 0.f;

#pragma unroll
            for (int kk = 0; kk < 8; kk++) {
#pragma unroll
                for (int nt = 0; nt < 8; nt++) {
                    const int rb = (nt * 8 + g) * AST + kk * 8 + tg;
                    uint32_t bh[2], bl[2];
                    bh[0] = Khi[rb]; bh[1] = Khi[rb + 4];
                    bl[0] = Klo[rb]; bl[1] = Klo[rb + 4];
                    mma_tf32(s[nt], qh[kk], bh);
                    mma_tf32(s[nt], ql[kk], bh);
                    mma_tf32(s[nt], qh[kk], bl);
                }
            }

            // ----- scale + causal mask -----
            const bool full = (c0 + 63 <= q0 + wm);
#pragma unroll
            for (int nt = 0; nt < 8; nt++) {
                s[nt][0] *= 0.125f; s[nt][1] *= 0.125f;
                s[nt][2] *= 0.125f; s[nt][3] *= 0.125f;
                if (!full) {
                    const int jg = c0 + nt * 8 + 2 * tg;
                    if (jg     > qi0) s[nt][0] = -1e30f;
                    if (jg + 1 > qi0) s[nt][1] = -1e30f;
                    if (jg     > qi1) s[nt][2] = -1e30f;
                    if (jg + 1 > qi1) s[nt][3] = -1e30f;
                }
            }

            // ----- online softmax (rows g and g+8) -----
            float mx0 = -1e30f, mx1 = -1e30f;
#pragma unroll
            for (int nt = 0; nt < 8; nt++) {
                mx0 = fmaxf(mx0, fmaxf(s[nt][0], s[nt][1]));
                mx1 = fmaxf(mx1, fmaxf(s[nt][2], s[nt][3]));
            }
            mx0 = fmaxf(mx0, __shfl_xor_sync(0xffffffffu, mx0, 1));
            mx0 = fmaxf(mx0, __shfl_xor_sync(0xffffffffu, mx0, 2));
            mx1 = fmaxf(mx1, __shfl_xor_sync(0xffffffffu, mx1, 1));
            mx1 = fmaxf(mx1, __shfl_xor_sync(0xffffffffu, mx1, 2));

            const float nm0 = fmaxf(m0, mx0), nm1 = fmaxf(m1, mx1);
            const float cr0 = __expf(m0 - nm0), cr1 = __expf(m1 - nm1);
            m0 = nm0; m1 = nm1;
            l0 *= cr0; l1 *= cr1;

            float ls0 = 0.f, ls1 = 0.f;
#pragma unroll
            for (int nt = 0; nt < 8; nt++) {
                const float p0 = __expf(s[nt][0] - m0);
                const float p1 = __expf(s[nt][1] - m0);
                const float p2 = __expf(s[nt][2] - m1);
                const float p3 = __expf(s[nt][3] - m1);
                ls0 += p0 + p1; ls1 += p2 + p3;
                o[nt][0] *= cr0; o[nt][1] *= cr0;
                o[nt][2] *= cr1; o[nt][3] *= cr1;
                *(float2*)&psw[g * AST + nt * 8 + 2 * tg]       = make_float2(p0, p1);
                *(float2*)&psw[(g + 8) * AST + nt * 8 + 2 * tg] = make_float2(p2, p3);
            }
            ls0 += __shfl_xor_sync(0xffffffffu, ls0, 1);
            ls0 += __shfl_xor_sync(0xffffffffu, ls0, 2);
            ls1 += __shfl_xor_sync(0xffffffffu, ls1, 1);
            ls1 += __shfl_xor_sync(0xffffffffu, ls1, 2);
            l0 += ls0; l1 += ls1;
            __syncwarp();

            // ----- O += P V (3xTF32; V from natural layout, 2-way conflicts) -----
#pragma unroll
            for (int kk = 0; kk < 8; kk++) {
                uint32_t pah[4], pal[4];
                split_tf32(psw[g * AST + kk * 8 + tg],           pah[0], pal[0]);
                split_tf32(psw[(g + 8) * AST + kk * 8 + tg],     pah[1], pal[1]);
                split_tf32(psw[g * AST + kk * 8 + tg + 4],       pah[2], pal[2]);
                split_tf32(psw[(g + 8) * AST + kk * 8 + tg + 4], pah[3], pal[3]);
#pragma unroll
                for (int nt = 0; nt < 8; nt++) {
                    const int r0i = (kk * 8 + tg) * AST + nt * 8 + g;
                    const int r1i = (kk * 8 + tg + 4) * AST + nt * 8 + g;
                    uint32_t bh[2], bl[2];
                    bh[0] = Vhi[r0i]; bh[1] = Vhi[r1i];
                    bl[0] = Vlo[r0i]; bl[1] = Vlo[r1i];
                    mma_tf32(o[nt], pah, bh);
                    mma_tf32(o[nt], pal, bh);
                    mma_tf32(o[nt], pah, bl);
                }
            }
        }
        __syncthreads();
    }

    // Epilogue: divide by l, write both rows.
    const float i0 = 1.f / l0, i1 = 1.f / l1;
    float* X0 = X + ((size_t)(b * S_ + qi0)) * DM + h * DK;
    float* X1 = X0 + 8 * DM;
#pragma unroll
    for (int nt = 0; nt < 8; nt++) {
        *(float2*)&X0[nt * 8 + 2 * tg] = make_float2(o[nt][0] * i0, o[nt][1] * i0);
        *(float2*)&X1[nt * 8 + 2 * tg] = make_float2(o[nt][2] * i1, o[nt][3] * i1);
    }
}

// ---------------------------------------------------------------------------
// Launch
// Inputs: 0:q 1:k 2:v 3:mask 4:wq 5:bq 6:wk 7:bk 8:wv 9:bv 10:wo 11:bo
// ---------------------------------------------------------------------------
extern "C" void kernel_launch(void* const* d_in, const int* in_sizes, int n_in,
                              void* d_out, int out_size)
{
    const float* q  = (const float*)d_in[0];
    const float* k  = (const float*)d_in[1];
    const float* v  = (const float*)d_in[2];
    const float* wq = (const float*)d_in[4];
    const float* bq = (const float*)d_in[5];
    const float* wk = (const float*)d_in[6];
    const float* bk = (const float*)d_in[7];
    const float* wv = (const float*)d_in[8];
    const float* bv = (const float*)d_in[9];
    const float* wo = (const float*)d_in[10];
    const float* bo = (const float*)d_in[11];
    float* out = (float*)d_out;

    float *gQ, *gK, *gV, *gX;
    cudaGetSymbolAddress((void**)&gQ, g_Q);
    cudaGetSymbolAddress((void**)&gK, g_K);
    cudaGetSymbolAddress((void**)&gV, g_V);
    cudaGetSymbolAddress((void**)&gX, g_X);

    cudaFuncSetAttribute(attn_tc,
                         cudaFuncAttributeMaxDynamicSharedMemorySize,
                         ATTN_TC_SMEM);

    const int M = B_ * S_;  // 4096

    dim3 qkvgrid(36, M / 64);        // (36, 64)
    gemm_qkv_tc<<<qkvgrid, 128>>>(q, k, v, wq, bq, wk, bk, wv, bv, gQ, gK, gV);

    dim3 agrid(S_ / 64, H_, B_);     // (32, 12, 2)
    attn_tc<<<agrid, 128, ATTN_TC_SMEM>>>(gQ, gK, gV, gX);

    dim3 wogrid(DM / 64, M / 64);    // (12, 64)
    gemm_wo_tc<<<wogrid, 128>>>(gX, wo, bo, out);
}

// round 15
// speedup vs baseline: 2.2459x; 1.1705x over previous
#include <cuda_runtime.h>
#include <cuda_bf16.h>
#include <cstdint>

// Problem constants
#define B_  2
#define S_  2048
#define DM  768
#define H_  12
#define DK  64

// Scratch (allocation-free rule: device globals)
__device__ float g_Q[B_ * S_ * DM];
__device__ float g_K[B_ * S_ * DM];
__device__ float g_V[B_ * S_ * DM];
__device__ float g_X[B_ * S_ * DM];

// ---------------------------------------------------------------------------
// TF32 helpers (verified; used by attention)
// ---------------------------------------------------------------------------
__device__ __forceinline__ uint32_t f2tf32(float x) {
    uint32_t r;
    asm("cvt.rna.tf32.f32 %0, %1;" : "=r"(r) : "f"(x));
    return r;
}

__device__ __forceinline__ void split_tf32(float x, uint32_t& hi, uint32_t& lo) {
    hi = f2tf32(x);
    lo = f2tf32(x - __uint_as_float(hi));
}

__device__ __forceinline__ void mma_tf32(float* c, const uint32_t* a,
                                         const uint32_t* b) {
    asm volatile(
        "mma.sync.aligned.m16n8k8.row.col.f32.tf32.tf32.f32 "
        "{%0,%1,%2,%3}, {%4,%5,%6,%7}, {%8,%9}, {%0,%1,%2,%3};"
        : "+f"(c[0]), "+f"(c[1]), "+f"(c[2]), "+f"(c[3])
        : "r"(a[0]), "r"(a[1]), "r"(a[2]), "r"(a[3]),
          "r"(b[0]), "r"(b[1]));
}

// ---------------------------------------------------------------------------
// BF16 helpers (GEMMs): m16n8k16 = 2x the MACs/inst of tf32 k8.
// 3-term split: x = hi + lo (+ ~2^-17 residue); ab = ah*bh + al*bh + ah*bl.
// ---------------------------------------------------------------------------
__device__ __forceinline__ void mma_bf16(float* c, const uint32_t* a,
                                         const uint32_t* b) {
    asm volatile(
        "mma.sync.aligned.m16n8k16.row.col.f32.bf16.bf16.f32 "
        "{%0,%1,%2,%3}, {%4,%5,%6,%7}, {%8,%9}, {%0,%1,%2,%3};"
        : "+f"(c[0]), "+f"(c[1]), "+f"(c[2]), "+f"(c[3])
        : "r"(a[0]), "r"(a[1]), "r"(a[2]), "r"(a[3]),
          "r"(b[0]), "r"(b[1]));
}

// Split two adjacent floats into packed bf16x2 hi and lo words.
__device__ __forceinline__ void split2_bf16(float x0, float x1,
                                            uint32_t& hi, uint32_t& lo) {
    __nv_bfloat162 h = __floats2bfloat162_rn(x0, x1);
    float r0 = x0 - __bfloat162float(h.x);
    float r1 = x1 - __bfloat162float(h.y);
    __nv_bfloat162 l = __floats2bfloat162_rn(r0, r1);
    hi = *reinterpret_cast<uint32_t*>(&h);
    lo = *reinterpret_cast<uint32_t*>(&l);
}

// ---------------------------------------------------------------------------
// BF16 tensor-core GEMM: C[M,N] = A[M,K] @ W[N,K]^T + bias[N]
// 64x64 CTA tile, 128 threads (4 warps 2x2), warp tile 32x32, BK=16,
// double-buffered smem holding PRE-SPLIT packed bf16x2 hi/lo tiles
// (split once at staging -> inner loop is pure LDS + MMA).
// PADU=12 u32 row stride: fragment reads conflict-free.
// ---------------------------------------------------------------------------
#define TCBK 16
#define PADU 12

__device__ __forceinline__ void stage_f4(uint32_t* hiA, uint32_t* loA,
                                         int row, int c2, float4 v) {
    uint32_t h0, l0, h1, l1;
    split2_bf16(v.x, v.y, h0, l0);
    split2_bf16(v.z, v.w, h1, l1);
    hiA[row * PADU + c2]     = h0;
    hiA[row * PADU + c2 + 1] = h1;
    loA[row * PADU + c2]     = l0;
    loA[row * PADU + c2 + 1] = l1;
}

__device__ __forceinline__ void gemm_bf_body(
    const float* __restrict__ A, const float* __restrict__ W,
    const float* __restrict__ bias, float* __restrict__ C,
    int N, int K, int bm, int bn,
    uint32_t (*Ah)[64 * PADU], uint32_t (*Al)[64 * PADU],
    uint32_t (*Wh)[64 * PADU], uint32_t (*Wl)[64 * PADU])
{
    const int t    = threadIdx.x;
    const int lane = t & 31;
    const int wid  = t >> 5;
    const int wm   = (wid >> 1) * 32;
    const int wn   = (wid & 1) * 32;
    const int g    = lane >> 2;
    const int tg   = lane & 3;

    const int r0 = t >> 2;          // 0..31
    const int cs = (t & 3) * 4;     // float col of this thread's float4
    const int c2 = (t & 3) * 2;     // packed-u32 col

    const float* Ap = A + (size_t)(bm + r0) * K + cs;
    const float* Wp = W + (size_t)(bn + r0) * K + cs;
    const size_t rowskip = (size_t)32 * K;

    float acc[2][4][4];
#pragma unroll
    for (int i = 0; i < 2; i++)
#pragma unroll
        for (int j = 0; j < 4; j++)
#pragma unroll
            for (int c = 0; c < 4; c++) acc[i][j][c] = 0.f;

    // stage buffer 0
    stage_f4(Ah[0], Al[0], r0,      c2, *(const float4*)(Ap));
    stage_f4(Ah[0], Al[0], r0 + 32, c2, *(const float4*)(Ap + rowskip));
    stage_f4(Wh[0], Wl[0], r0,      c2, *(const float4*)(Wp));
    stage_f4(Wh[0], Wl[0], r0 + 32, c2, *(const float4*)(Wp + rowskip));
    __syncthreads();

    int cur = 0;
    for (int kt = 0; kt < K; kt += TCBK) {
        const bool has_next = (kt + TCBK) < K;
        float4 a0n, a1n, w0n, w1n;
        if (has_next) {
            a0n = *(const float4*)(Ap + kt + TCBK);
            a1n = *(const float4*)(Ap + rowskip + kt + TCBK);
            w0n = *(const float4*)(Wp + kt + TCBK);
            w1n = *(const float4*)(Wp + rowskip + kt + TCBK);
        }

        const uint32_t* ah_s = Ah[cur];
        const uint32_t* al_s = Al[cur];
        const uint32_t* wh_s = Wh[cur];
        const uint32_t* wl_s = Wl[cur];

        // A fragments: a0=(g,k[2tg:2tg+1]) a1=(g+8,..) a2=(g,8+2tg..) a3=(g+8,..)
        uint32_t ah[2][4], al[2][4];
#pragma unroll
        for (int mt = 0; mt < 2; mt++) {
            const int row = wm + mt * 16 + g;
            ah[mt][0] = ah_s[row * PADU + tg];
            ah[mt][1] = ah_s[(row + 8) * PADU + tg];
            ah[mt][2] = ah_s[row * PADU + 4 + tg];
            ah[mt][3] = ah_s[(row + 8) * PADU + 4 + tg];
            al[mt][0] = al_s[row * PADU + tg];
            al[mt][1] = al_s[(row + 8) * PADU + tg];
            al[mt][2] = al_s[row * PADU + 4 + tg];
            al[mt][3] = al_s[(row + 8) * PADU + 4 + tg];
        }
        // B fragments: b0=(k[2tg:2tg+1], n=g), b1=(k[8+2tg..], n=g)
        uint32_t bh[4][2], bl[4][2];
#pragma unroll
        for (int nt = 0; nt < 4; nt++) {
            const int n = wn + nt * 8 + g;
            bh[nt][0] = wh_s[n * PADU + tg];
            bh[nt][1] = wh_s[n * PADU + 4 + tg];
            bl[nt][0] = wl_s[n * PADU + tg];
            bl[nt][1] = wl_s[n * PADU + 4 + tg];
        }
#pragma unroll
        for (int mt = 0; mt < 2; mt++)
#pragma unroll
            for (int nt = 0; nt < 4; nt++) {
                mma_bf16(acc[mt][nt], ah[mt], bh[nt]);
                mma_bf16(acc[mt][nt], al[mt], bh[nt]);
                mma_bf16(acc[mt][nt], ah[mt], bl[nt]);
            }

        if (has_next) {
            const int nxt = cur ^ 1;
            stage_f4(Ah[nxt], Al[nxt], r0,      c2, a0n);
            stage_f4(Ah[nxt], Al[nxt], r0 + 32, c2, a1n);
            stage_f4(Wh[nxt], Wl[nxt], r0,      c2, w0n);
            stage_f4(Wh[nxt], Wl[nxt], r0 + 32, c2, w1n);
        }
        __syncthreads();
        cur ^= 1;
    }

    // Epilogue (identical C layout to tf32 path): c0,c1 adjacent cols.
#pragma unroll
    for (int mt = 0; mt < 2; mt++) {
        const int row = bm + wm + mt * 16 + g;
#pragma unroll
        for (int nt = 0; nt < 4; nt++) {
            const int col = bn + wn + nt * 8 + tg * 2;
            const float b0 = bias[col], b1 = bias[col + 1];
            float2 v0 = { acc[mt][nt][0] + b0, acc[mt][nt][1] + b1 };
            float2 v1 = { acc[mt][nt][2] + b0, acc[mt][nt][3] + b1 };
            *(float2*)&C[(size_t)row * N + col]       = v0;
            *(float2*)&C[(size_t)(row + 8) * N + col] = v1;
        }
    }
}

__global__ __launch_bounds__(128) void gemm_qkv_tc(
    const float* __restrict__ q, const float* __restrict__ k,
    const float* __restrict__ v,
    const float* __restrict__ wq, const float* __restrict__ bq,
    const float* __restrict__ wk, const float* __restrict__ bk,
    const float* __restrict__ wv, const float* __restrict__ bv,
    float* __restrict__ gQ, float* __restrict__ gK, float* __restrict__ gV)
{
    __shared__ uint32_t Ah[2][64 * PADU], Al[2][64 * PADU];
    __shared__ uint32_t Wh[2][64 * PADU], Wl[2][64 * PADU];

    const int bx  = blockIdx.x;
    const int sel = bx / 12;
    const int bn  = (bx % 12) * 64;
    const int bm  = blockIdx.y * 64;

    const float* A; const float* W; const float* bias; float* C;
    if (sel == 0)      { A = q; W = wq; bias = bq; C = gQ; }
    else if (sel == 1) { A = k; W = wk; bias = bk; C = gK; }
    else               { A = v; W = wv; bias = bv; C = gV; }

    gemm_bf_body(A, W, bias, C, DM, DM, bm, bn, Ah, Al, Wh, Wl);
}

__global__ __launch_bounds__(128) void gemm_wo_tc(
    const float* __restrict__ A, const float* __restrict__ W,
    const float* __restrict__ bias, float* __restrict__ C)
{
    __shared__ uint32_t Ah[2][64 * PADU], Al[2][64 * PADU];
    __shared__ uint32_t Wh[2][64 * PADU], Wl[2][64 * PADU];
    gemm_bf_body(A, W, bias, C, DM, DM,
                 blockIdx.y * 64, blockIdx.x * 64, Ah, Al, Wh, Wl);
}

// ---------------------------------------------------------------------------
// Tensor-core causal flash attention (UNCHANGED from passing R11 kernel).
// ---------------------------------------------------------------------------
#define AST 68
#define ATTN_TC_SMEM ((4 * 64 * AST + 4 * 16 * AST) * 4)

__global__ __launch_bounds__(128) void attn_tc(
    const float* __restrict__ Q, const float* __restrict__ K,
    const float* __restrict__ V, float* __restrict__ X)
{
    extern __shared__ uint32_t sm[];
    uint32_t* Khi = sm;
    uint32_t* Klo = sm + 64 * AST;
    uint32_t* Vhi = sm + 2 * 64 * AST;
    uint32_t* Vlo = sm + 3 * 64 * AST;
    float*    Ps  = (float*)(sm + 4 * 64 * AST);

    const int tid  = threadIdx.x;
    const int lane = tid & 31;
    const int wid  = tid >> 5;
    const int g    = lane >> 2;
    const int tg   = lane & 3;
    const int wm   = wid * 16;
    const int h    = blockIdx.y;
    const int b    = blockIdx.z;
    const int qblk = (int)gridDim.x - 1 - (int)blockIdx.x;
    const int q0   = qblk * 64;
    const int qi0  = q0 + wm + g;
    const int qi1  = qi0 + 8;
    float* psw = Ps + wid * (16 * AST);

    uint32_t qh[8][4], ql[8][4];
    {
        const float* Q0 = Q + ((size_t)(b * S_ + qi0)) * DM + h * DK;
        const float* Q1 = Q0 + 8 * DM;
#pragma unroll
        for (int kk = 0; kk < 8; kk++) {
            split_tf32(Q0[kk * 8 + tg],     qh[kk][0], ql[kk][0]);
            split_tf32(Q1[kk * 8 + tg],     qh[kk][1], ql[kk][1]);
            split_tf32(Q0[kk * 8 + tg + 4], qh[kk][2], ql[kk][2]);
            split_tf32(Q1[kk * 8 + tg + 4], qh[kk][3], ql[kk][3]);
        }
    }

    float o[8][4];
#pragma unroll
    for (int nt = 0; nt < 8; nt++)
#pragma unroll
        for (int c = 0; c < 4; c++) o[nt][c] = 0.f;
    float m0 = -1e30f, m1 = -1e30f, l0 = 0.f, l1 = 0.f;

    for (int c0 = 0; c0 < q0 + 64; c0 += 64) {
        const float4* kb4 = (const float4*)(K + ((size_t)(b * S_ + c0)) * DM + h * DK);
        const float4* vb4 = (const float4*)(V + ((size_t)(b * S_ + c0)) * DM + h * DK);
#pragma unroll
        for (int i = 0; i < 8; i++) {
            const int idx = tid + i * 128;
            const int j   = idx >> 4;
            const int c4  = idx & 15;
            float4 kv = kb4[(size_t)j * (DM / 4) + c4];
            float4 vv = vb4[(size_t)j * (DM / 4) + c4];
            const int base = j * AST + c4 * 4;
            uint32_t hi, lo;
            split_tf32(kv.x, hi, lo); Khi[base + 0] = hi; Klo[base + 0] = lo;
            split_tf32(kv.y, hi, lo); Khi[base + 1] = hi; Klo[base + 1] = lo;
            split_tf32(kv.z, hi, lo); Khi[base + 2] = hi; Klo[base + 2] = lo;
            split_tf32(kv.w, hi, lo); Khi[base + 3] = hi; Klo[base + 3] = lo;
            split_tf32(vv.x, hi, lo); Vhi[base + 0] = hi; Vlo[base + 0] = lo;
            split_tf32(vv.y, hi, lo); Vhi[base + 1] = hi; Vlo[base + 1] = lo;
            split_tf32(vv.z, hi, lo); Vhi[base + 2] = hi; Vlo[base + 2] = lo;
            split_tf32(vv.w, hi, lo); Vhi[base + 3] = hi; Vlo[base + 3] = lo;
        }
        __syncthreads();

        if (c0 < q0 + wm + 16) {
            float s[8][4];
#pragma unroll
            for (int nt = 0; nt < 8; nt++)
#pragma unroll
                for (int c = 0; c < 4; c++) s[nt][c] = 0.f;

#pragma unroll
            for (int kk = 0; kk < 8; kk++) {
#pragma unroll
                for (int nt = 0; nt < 8; nt++) {
                    const int rb = (nt * 8 + g) * AST + kk * 8 + tg;
                    uint32_t bh[2], bl[2];
                    bh[0] = Khi[rb]; bh[1] = Khi[rb + 4];
                    bl[0] = Klo[rb]; bl[1] = Klo[rb + 4];
                    mma_tf32(s[nt], qh[kk], bh);
                    mma_tf32(s[nt], ql[kk], bh);
                    mma_tf32(s[nt], qh[kk], bl);
                }
            }

            const bool full = (c0 + 63 <= q0 + wm);
#pragma unroll
            for (int nt = 0; nt < 8; nt++) {
                s[nt][0] *= 0.125f; s[nt][1] *= 0.125f;
                s[nt][2] *= 0.125f; s[nt][3] *= 0.125f;
                if (!full) {
                    const int jg = c0 + nt * 8 + 2 * tg;
                    if (jg     > qi0) s[nt][0] = -1e30f;
                    if (jg + 1 > qi0) s[nt][1] = -1e30f;
                    if (jg     > qi1) s[nt][2] = -1e30f;
                    if (jg + 1 > qi1) s[nt][3] = -1e30f;
                }
            }

            float mx0 = -1e30f, mx1 = -1e30f;
#pragma unroll
            for (int nt = 0; nt < 8; nt++) {
                mx0 = fmaxf(mx0, fmaxf(s[nt][0], s[nt][1]));
                mx1 = fmaxf(mx1, fmaxf(s[nt][2], s[nt][3]));
            }
            mx0 = fmaxf(mx0, __shfl_xor_sync(0xffffffffu, mx0, 1));
            mx0 = fmaxf(mx0, __shfl_xor_sync(0xffffffffu, mx0, 2));
            mx1 = fmaxf(mx1, __shfl_xor_sync(0xffffffffu, mx1, 1));
            mx1 = fmaxf(mx1, __shfl_xor_sync(0xffffffffu, mx1, 2));

            const float nm0 = fmaxf(m0, mx0), nm1 = fmaxf(m1, mx1);
            const float cr0 = __expf(m0 - nm0), cr1 = __expf(m1 - nm1);
            m0 = nm0; m1 = nm1;
            l0 *= cr0; l1 *= cr1;

            float ls0 = 0.f, ls1 = 0.f;
#pragma unroll
            for (int nt = 0; nt < 8; nt++) {
                const float p0 = __expf(s[nt][0] - m0);
                const float p1 = __expf(s[nt][1] - m0);
                const float p2 = __expf(s[nt][2] - m1);
                const float p3 = __expf(s[nt][3] - m1);
                ls0 += p0 + p1; ls1 += p2 + p3;
                o[nt][0] *= cr0; o[nt][1] *= cr0;
                o[nt][2] *= cr1; o[nt][3] *= cr1;
                *(float2*)&psw[g * AST + nt * 8 + 2 * tg]       = make_float2(p0, p1);
                *(float2*)&psw[(g + 8) * AST + nt * 8 + 2 * tg] = make_float2(p2, p3);
            }
            ls0 += __shfl_xor_sync(0xffffffffu, ls0, 1);
            ls0 += __shfl_xor_sync(0xffffffffu, ls0, 2);
            ls1 += __shfl_xor_sync(0xffffffffu, ls1, 1);
            ls1 += __shfl_xor_sync(0xffffffffu, ls1, 2);
            l0 += ls0; l1 += ls1;
            __syncwarp();

#pragma unroll
            for (int kk = 0; kk < 8; kk++) {
                uint32_t pah[4], pal[4];
                split_tf32(psw[g * AST + kk * 8 + tg],           pah[0], pal[0]);
                split_tf32(psw[(g + 8) * AST + kk * 8 + tg],     pah[1], pal[1]);
                split_tf32(psw[g * AST + kk * 8 + tg + 4],       pah[2], pal[2]);
                split_tf32(psw[(g + 8) * AST + kk * 8 + tg + 4], pah[3], pal[3]);
#pragma unroll
                for (int nt = 0; nt < 8; nt++) {
                    const int r0i = (kk * 8 + tg) * AST + nt * 8 + g;
                    const int r1i = (kk * 8 + tg + 4) * AST + nt * 8 + g;
                    uint32_t bh[2], bl[2];
                    bh[0] = Vhi[r0i]; bh[1] = Vhi[r1i];
                    bl[0] = Vlo[r0i]; bl[1] = Vlo[r1i];
                    mma_tf32(o[nt], pah, bh);
                    mma_tf32(o[nt], pal, bh);
                    mma_tf32(o[nt], pah, bl);
                }
            }
        }
        __syncthreads();
    }

    const float i0 = 1.f / l0, i1 = 1.f / l1;
    float* X0 = X + ((size_t)(b * S_ + qi0)) * DM + h * DK;
    float* X1 = X0 + 8 * DM;
#pragma unroll
    for (int nt = 0; nt < 8; nt++) {
        *(float2*)&X0[nt * 8 + 2 * tg] = make_float2(o[nt][0] * i0, o[nt][1] * i0);
        *(float2*)&X1[nt * 8 + 2 * tg] = make_float2(o[nt][2] * i1, o[nt][3] * i1);
    }
}

// ---------------------------------------------------------------------------
// Launch
// Inputs: 0:q 1:k 2:v 3:mask 4:wq 5:bq 6:wk 7:bk 8:wv 9:bv 10:wo 11:bo
// ---------------------------------------------------------------------------
extern "C" void kernel_launch(void* const* d_in, const int* in_sizes, int n_in,
                              void* d_out, int out_size)
{
    const float* q  = (const float*)d_in[0];
    const float* k  = (const float*)d_in[1];
    const float* v  = (const float*)d_in[2];
    const float* wq = (const float*)d_in[4];
    const float* bq = (const float*)d_in[5];
    const float* wk = (const float*)d_in[6];
    const float* bk = (const float*)d_in[7];
    const float* wv = (const float*)d_in[8];
    const float* bv = (const float*)d_in[9];
    const float* wo = (const float*)d_in[10];
    const float* bo = (const float*)d_in[11];
    float* out = (float*)d_out;

    float *gQ, *gK, *gV, *gX;
    cudaGetSymbolAddress((void**)&gQ, g_Q);
    cudaGetSymbolAddress((void**)&gK, g_K);
    cudaGetSymbolAddress((void**)&gV, g_V);
    cudaGetSymbolAddress((void**)&gX, g_X);

    cudaFuncSetAttribute(attn_tc,
                         cudaFuncAttributeMaxDynamicSharedMemorySize,
                         ATTN_TC_SMEM);

    const int M = B_ * S_;  // 4096

    dim3 qkvgrid(36, M / 64);        // (36, 64)
    gemm_qkv_tc<<<qkvgrid, 128>>>(q, k, v, wq, bq, wk, bk, wv, bv, gQ, gK, gV);

    dim3 agrid(S_ / 64, H_, B_);     // (32, 12, 2)
    attn_tc<<<agrid, 128, ATTN_TC_SMEM>>>(gQ, gK, gV, gX);

    dim3 wogrid(DM / 64, M / 64);    // (12, 64)
    gemm_wo_tc<<<wogrid, 128>>>(gX, wo, bo, out);
}

// round 16
// speedup vs baseline: 3.1313x; 1.3942x over previous
#include <cuda_runtime.h>
#include <cuda_bf16.h>
#include <cstdint>

// Problem constants
#define B_  2
#define S_  2048
#define DM  768
#define H_  12
#define DK  64

// Scratch (allocation-free rule: device globals)
__device__ float g_Q[B_ * S_ * DM];
__device__ float g_K[B_ * S_ * DM];
__device__ float g_V[B_ * S_ * DM];
__device__ float g_X[B_ * S_ * DM];

// ---------------------------------------------------------------------------
// BF16 m16n8k16 helpers (verified R14): 3-term split ab = ah*bh + al*bh + ah*bl
// ---------------------------------------------------------------------------
__device__ __forceinline__ void mma_bf16(float* c, const uint32_t* a,
                                         const uint32_t* b) {
    asm volatile(
        "mma.sync.aligned.m16n8k16.row.col.f32.bf16.bf16.f32 "
        "{%0,%1,%2,%3}, {%4,%5,%6,%7}, {%8,%9}, {%0,%1,%2,%3};"
        : "+f"(c[0]), "+f"(c[1]), "+f"(c[2]), "+f"(c[3])
        : "r"(a[0]), "r"(a[1]), "r"(a[2]), "r"(a[3]),
          "r"(b[0]), "r"(b[1]));
}

// Split two adjacent floats into packed bf16x2 hi and lo words.
__device__ __forceinline__ void split2_bf16(float x0, float x1,
                                            uint32_t& hi, uint32_t& lo) {
    __nv_bfloat162 h = __floats2bfloat162_rn(x0, x1);
    float r0 = x0 - __bfloat162float(h.x);
    float r1 = x1 - __bfloat162float(h.y);
    __nv_bfloat162 l = __floats2bfloat162_rn(r0, r1);
    hi = *reinterpret_cast<uint32_t*>(&h);
    lo = *reinterpret_cast<uint32_t*>(&l);
}

__device__ __forceinline__ void split1_bf16(float x, __nv_bfloat16& h,
                                            __nv_bfloat16& l) {
    h = __float2bfloat16_rn(x);
    l = __float2bfloat16_rn(x - __bfloat162float(h));
}

// ---------------------------------------------------------------------------
// BF16 tensor-core GEMM (verified R14): C = A @ W^T + bias
// ---------------------------------------------------------------------------
#define TCBK 16
#define PADU 12

__device__ __forceinline__ void stage_f4(uint32_t* hiA, uint32_t* loA,
                                         int row, int c2, float4 v) {
    uint32_t h0, l0, h1, l1;
    split2_bf16(v.x, v.y, h0, l0);
    split2_bf16(v.z, v.w, h1, l1);
    hiA[row * PADU + c2]     = h0;
    hiA[row * PADU + c2 + 1] = h1;
    loA[row * PADU + c2]     = l0;
    loA[row * PADU + c2 + 1] = l1;
}

__device__ __forceinline__ void gemm_bf_body(
    const float* __restrict__ A, const float* __restrict__ W,
    const float* __restrict__ bias, float* __restrict__ C,
    int N, int K, int bm, int bn,
    uint32_t (*Ah)[64 * PADU], uint32_t (*Al)[64 * PADU],
    uint32_t (*Wh)[64 * PADU], uint32_t (*Wl)[64 * PADU])
{
    const int t    = threadIdx.x;
    const int lane = t & 31;
    const int wid  = t >> 5;
    const int wm   = (wid >> 1) * 32;
    const int wn   = (wid & 1) * 32;
    const int g    = lane >> 2;
    const int tg   = lane & 3;

    const int r0 = t >> 2;
    const int cs = (t & 3) * 4;
    const int c2 = (t & 3) * 2;

    const float* Ap = A + (size_t)(bm + r0) * K + cs;
    const float* Wp = W + (size_t)(bn + r0) * K + cs;
    const size_t rowskip = (size_t)32 * K;

    float acc[2][4][4];
#pragma unroll
    for (int i = 0; i < 2; i++)
#pragma unroll
        for (int j = 0; j < 4; j++)
#pragma unroll
            for (int c = 0; c < 4; c++) acc[i][j][c] = 0.f;

    stage_f4(Ah[0], Al[0], r0,      c2, *(const float4*)(Ap));
    stage_f4(Ah[0], Al[0], r0 + 32, c2, *(const float4*)(Ap + rowskip));
    stage_f4(Wh[0], Wl[0], r0,      c2, *(const float4*)(Wp));
    stage_f4(Wh[0], Wl[0], r0 + 32, c2, *(const float4*)(Wp + rowskip));
    __syncthreads();

    int cur = 0;
    for (int kt = 0; kt < K; kt += TCBK) {
        const bool has_next = (kt + TCBK) < K;
        float4 a0n, a1n, w0n, w1n;
        if (has_next) {
            a0n = *(const float4*)(Ap + kt + TCBK);
            a1n = *(const float4*)(Ap + rowskip + kt + TCBK);
            w0n = *(const float4*)(Wp + kt + TCBK);
            w1n = *(const float4*)(Wp + rowskip + kt + TCBK);
        }

        const uint32_t* ah_s = Ah[cur];
        const uint32_t* al_s = Al[cur];
        const uint32_t* wh_s = Wh[cur];
        const uint32_t* wl_s = Wl[cur];

        uint32_t ah[2][4], al[2][4];
#pragma unroll
        for (int mt = 0; mt < 2; mt++) {
            const int row = wm + mt * 16 + g;
            ah[mt][0] = ah_s[row * PADU + tg];
            ah[mt][1] = ah_s[(row + 8) * PADU + tg];
            ah[mt][2] = ah_s[row * PADU + 4 + tg];
            ah[mt][3] = ah_s[(row + 8) * PADU + 4 + tg];
            al[mt][0] = al_s[row * PADU + tg];
            al[mt][1] = al_s[(row + 8) * PADU + tg];
            al[mt][2] = al_s[row * PADU + 4 + tg];
            al[mt][3] = al_s[(row + 8) * PADU + 4 + tg];
        }
        uint32_t bh[4][2], bl[4][2];
#pragma unroll
        for (int nt = 0; nt < 4; nt++) {
            const int n = wn + nt * 8 + g;
            bh[nt][0] = wh_s[n * PADU + tg];
            bh[nt][1] = wh_s[n * PADU + 4 + tg];
            bl[nt][0] = wl_s[n * PADU + tg];
            bl[nt][1] = wl_s[n * PADU + 4 + tg];
        }
#pragma unroll
        for (int mt = 0; mt < 2; mt++)
#pragma unroll
            for (int nt = 0; nt < 4; nt++) {
                mma_bf16(acc[mt][nt], ah[mt], bh[nt]);
                mma_bf16(acc[mt][nt], al[mt], bh[nt]);
                mma_bf16(acc[mt][nt], ah[mt], bl[nt]);
            }

        if (has_next) {
            const int nxt = cur ^ 1;
            stage_f4(Ah[nxt], Al[nxt], r0,      c2, a0n);
            stage_f4(Ah[nxt], Al[nxt], r0 + 32, c2, a1n);
            stage_f4(Wh[nxt], Wl[nxt], r0,      c2, w0n);
            stage_f4(Wh[nxt], Wl[nxt], r0 + 32, c2, w1n);
        }
        __syncthreads();
        cur ^= 1;
    }

#pragma unroll
    for (int mt = 0; mt < 2; mt++) {
        const int row = bm + wm + mt * 16 + g;
#pragma unroll
        for (int nt = 0; nt < 4; nt++) {
            const int col = bn + wn + nt * 8 + tg * 2;
            const float b0 = bias[col], b1 = bias[col + 1];
            float2 v0 = { acc[mt][nt][0] + b0, acc[mt][nt][1] + b1 };
            float2 v1 = { acc[mt][nt][2] + b0, acc[mt][nt][3] + b1 };
            *(float2*)&C[(size_t)row * N + col]       = v0;
            *(float2*)&C[(size_t)(row + 8) * N + col] = v1;
        }
    }
}

__global__ __launch_bounds__(128) void gemm_qkv_tc(
    const float* __restrict__ q, const float* __restrict__ k,
    const float* __restrict__ v,
    const float* __restrict__ wq, const float* __restrict__ bq,
    const float* __restrict__ wk, const float* __restrict__ bk,
    const float* __restrict__ wv, const float* __restrict__ bv,
    float* __restrict__ gQ, float* __restrict__ gK, float* __restrict__ gV)
{
    __shared__ uint32_t Ah[2][64 * PADU], Al[2][64 * PADU];
    __shared__ uint32_t Wh[2][64 * PADU], Wl[2][64 * PADU];

    const int bx  = blockIdx.x;
    const int sel = bx / 12;
    const int bn  = (bx % 12) * 64;
    const int bm  = blockIdx.y * 64;

    const float* A; const float* W; const float* bias; float* C;
    if (sel == 0)      { A = q; W = wq; bias = bq; C = gQ; }
    else if (sel == 1) { A = k; W = wk; bias = bk; C = gK; }
    else               { A = v; W = wv; bias = bv; C = gV; }

    gemm_bf_body(A, W, bias, C, DM, DM, bm, bn, Ah, Al, Wh, Wl);
}

__global__ __launch_bounds__(128) void gemm_wo_tc(
    const float* __restrict__ A, const float* __restrict__ W,
    const float* __restrict__ bias, float* __restrict__ C)
{
    __shared__ uint32_t Ah[2][64 * PADU], Al[2][64 * PADU];
    __shared__ uint32_t Wh[2][64 * PADU], Wl[2][64 * PADU];
    gemm_bf_body(A, W, bias, C, DM, DM,
                 blockIdx.y * 64, blockIdx.x * 64, Ah, Al, Wh, Wl);
}

// ---------------------------------------------------------------------------
// BF16 tensor-core causal flash attention.
// CTA: 64 queries x (b,h), 4 warps x m16 rows, 64-key tiles.
// K staged as packed bf16x2 hi/lo [key][dim-pair] (stride 36 words).
// V staged TRANSPOSED as packed bf16x2 hi/lo [dim][key-pair] so the PV
// B-operand has key-pairs adjacent. Both matmuls m16n8k16, 3-term split.
// ---------------------------------------------------------------------------
#define WST 36   // u32 row stride for K/VT tiles (32 data + 4 pad)
#define AST 68   // float row stride for P tile
#define ATTN_TC_SMEM ((4 * 64 * WST) * 4 + (4 * 16 * AST) * 4)

__global__ __launch_bounds__(128) void attn_tc(
    const float* __restrict__ Q, const float* __restrict__ K,
    const float* __restrict__ V, float* __restrict__ X)
{
    extern __shared__ uint32_t sm[];
    uint32_t* Khi  = sm;
    uint32_t* Klo  = sm + 64 * WST;
    uint32_t* VThi = sm + 2 * 64 * WST;
    uint32_t* VTlo = sm + 3 * 64 * WST;
    float*    Ps   = (float*)(sm + 4 * 64 * WST);

    const int tid  = threadIdx.x;
    const int lane = tid & 31;
    const int wid  = tid >> 5;
    const int g    = lane >> 2;
    const int tg   = lane & 3;
    const int wm   = wid * 16;
    const int h    = blockIdx.y;
    const int b    = blockIdx.z;
    const int qblk = (int)gridDim.x - 1 - (int)blockIdx.x;   // LPT order
    const int q0   = qblk * 64;
    const int qi0  = q0 + wm + g;
    const int qi1  = qi0 + 8;
    float* psw = Ps + wid * (16 * AST);

    // Preconvert Q fragments to bf16 hi/lo (4 k16-steps x 4 regs).
    uint32_t qh[4][4], ql[4][4];
    {
        const float* Q0 = Q + ((size_t)(b * S_ + qi0)) * DM + h * DK;
        const float* Q1 = Q0 + 8 * DM;
#pragma unroll
        for (int kk = 0; kk < 4; kk++) {
            split2_bf16(Q0[kk * 16 + 2 * tg],     Q0[kk * 16 + 2 * tg + 1],
                        qh[kk][0], ql[kk][0]);
            split2_bf16(Q1[kk * 16 + 2 * tg],     Q1[kk * 16 + 2 * tg + 1],
                        qh[kk][1], ql[kk][1]);
            split2_bf16(Q0[kk * 16 + 8 + 2 * tg], Q0[kk * 16 + 8 + 2 * tg + 1],
                        qh[kk][2], ql[kk][2]);
            split2_bf16(Q1[kk * 16 + 8 + 2 * tg], Q1[kk * 16 + 8 + 2 * tg + 1],
                        qh[kk][3], ql[kk][3]);
        }
    }

    float o[8][4];
#pragma unroll
    for (int nt = 0; nt < 8; nt++)
#pragma unroll
        for (int c = 0; c < 4; c++) o[nt][c] = 0.f;
    float m0 = -1e30f, m1 = -1e30f, l0 = 0.f, l1 = 0.f;

    for (int c0 = 0; c0 < q0 + 64; c0 += 64) {
        const float4* kb4 = (const float4*)(K + ((size_t)(b * S_ + c0)) * DM + h * DK);
        const float4* vb4 = (const float4*)(V + ((size_t)(b * S_ + c0)) * DM + h * DK);

        // K: coalesced load, natural [key][dim-pair] packed layout.
#pragma unroll
        for (int i = 0; i < 8; i++) {
            const int idx = tid + i * 128;        // 0..1023
            const int j   = idx >> 4;             // key
            const int c4  = idx & 15;             // dim float4
            float4 kv = kb4[(size_t)j * (DM / 4) + c4];
            uint32_t h0, l0w, h1, l1w;
            split2_bf16(kv.x, kv.y, h0, l0w);
            split2_bf16(kv.z, kv.w, h1, l1w);
            Khi[j * WST + 2 * c4]     = h0;
            Khi[j * WST + 2 * c4 + 1] = h1;
            Klo[j * WST + 2 * c4]     = l0w;
            Klo[j * WST + 2 * c4 + 1] = l1w;
        }
        // V: key-per-lane load, staged transposed [dim][key] as bf16.
        __nv_bfloat16* VThib = (__nv_bfloat16*)VThi;
        __nv_bfloat16* VTlob = (__nv_bfloat16*)VTlo;
#pragma unroll
        for (int i = 0; i < 8; i++) {
            const int idx = tid + i * 128;
            const int j   = idx & 63;             // key
            const int cg  = idx >> 6;             // dim float4 (0..15)
            float4 vv = vb4[(size_t)j * (DM / 4) + cg];
            __nv_bfloat16 hb, lb;
            split1_bf16(vv.x, hb, lb);
            VThib[(cg * 4 + 0) * (2 * WST) + j] = hb;
            VTlob[(cg * 4 + 0) * (2 * WST) + j] = lb;
            split1_bf16(vv.y, hb, lb);
            VThib[(cg * 4 + 1) * (2 * WST) + j] = hb;
            VTlob[(cg * 4 + 1) * (2 * WST) + j] = lb;
            split1_bf16(vv.z, hb, lb);
            VThib[(cg * 4 + 2) * (2 * WST) + j] = hb;
            VTlob[(cg * 4 + 2) * (2 * WST) + j] = lb;
            split1_bf16(vv.w, hb, lb);
            VThib[(cg * 4 + 3) * (2 * WST) + j] = hb;
            VTlob[(cg * 4 + 3) * (2 * WST) + j] = lb;
        }
        __syncthreads();

        if (c0 < q0 + wm + 16) {
            // ----- S = Q K^T (bf16 3-term) -----
            float s[8][4];
#pragma unroll
            for (int nt = 0; nt < 8; nt++)
#pragma unroll
                for (int c = 0; c < 4; c++) s[nt][c] = 0.f;

#pragma unroll
            for (int kk = 0; kk < 4; kk++) {
#pragma unroll
                for (int nt = 0; nt < 8; nt++) {
                    const int rb = (nt * 8 + g) * WST + kk * 8;
                    uint32_t bh[2], bl[2];
                    bh[0] = Khi[rb + tg];     bh[1] = Khi[rb + 4 + tg];
                    bl[0] = Klo[rb + tg];     bl[1] = Klo[rb + 4 + tg];
                    mma_bf16(s[nt], qh[kk], bh);
                    mma_bf16(s[nt], ql[kk], bh);
                    mma_bf16(s[nt], qh[kk], bl);
                }
            }

            // ----- scale + causal mask -----
            const bool full = (c0 + 63 <= q0 + wm);
#pragma unroll
            for (int nt = 0; nt < 8; nt++) {
                s[nt][0] *= 0.125f; s[nt][1] *= 0.125f;
                s[nt][2] *= 0.125f; s[nt][3] *= 0.125f;
                if (!full) {
                    const int jg = c0 + nt * 8 + 2 * tg;
                    if (jg     > qi0) s[nt][0] = -1e30f;
                    if (jg + 1 > qi0) s[nt][1] = -1e30f;
                    if (jg     > qi1) s[nt][2] = -1e30f;
                    if (jg + 1 > qi1) s[nt][3] = -1e30f;
                }
            }

            // ----- online softmax (rows g and g+8) -----
            float mx0 = -1e30f, mx1 = -1e30f;
#pragma unroll
            for (int nt = 0; nt < 8; nt++) {
                mx0 = fmaxf(mx0, fmaxf(s[nt][0], s[nt][1]));
                mx1 = fmaxf(mx1, fmaxf(s[nt][2], s[nt][3]));
            }
            mx0 = fmaxf(mx0, __shfl_xor_sync(0xffffffffu, mx0, 1));
            mx0 = fmaxf(mx0, __shfl_xor_sync(0xffffffffu, mx0, 2));
            mx1 = fmaxf(mx1, __shfl_xor_sync(0xffffffffu, mx1, 1));
            mx1 = fmaxf(mx1, __shfl_xor_sync(0xffffffffu, mx1, 2));

            const float nm0 = fmaxf(m0, mx0), nm1 = fmaxf(m1, mx1);
            const float cr0 = __expf(m0 - nm0), cr1 = __expf(m1 - nm1);
            m0 = nm0; m1 = nm1;
            l0 *= cr0; l1 *= cr1;

            float ls0 = 0.f, ls1 = 0.f;
#pragma unroll
            for (int nt = 0; nt < 8; nt++) {
                const float p0 = __expf(s[nt][0] - m0);
                const float p1 = __expf(s[nt][1] - m0);
                const float p2 = __expf(s[nt][2] - m1);
                const float p3 = __expf(s[nt][3] - m1);
                ls0 += p0 + p1; ls1 += p2 + p3;
                o[nt][0] *= cr0; o[nt][1] *= cr0;
                o[nt][2] *= cr1; o[nt][3] *= cr1;
                *(float2*)&psw[g * AST + nt * 8 + 2 * tg]       = make_float2(p0, p1);
                *(float2*)&psw[(g + 8) * AST + nt * 8 + 2 * tg] = make_float2(p2, p3);
            }
            ls0 += __shfl_xor_sync(0xffffffffu, ls0, 1);
            ls0 += __shfl_xor_sync(0xffffffffu, ls0, 2);
            ls1 += __shfl_xor_sync(0xffffffffu, ls1, 1);
            ls1 += __shfl_xor_sync(0xffffffffu, ls1, 2);
            l0 += ls0; l1 += ls1;
            __syncwarp();

            // ----- O += P V (bf16 3-term; B from transposed VT tile) -----
#pragma unroll
            for (int kk = 0; kk < 4; kk++) {
                uint32_t pah[4], pal[4];
                split2_bf16(psw[g * AST + kk * 16 + 2 * tg],
                            psw[g * AST + kk * 16 + 2 * tg + 1],
                            pah[0], pal[0]);
                split2_bf16(psw[(g + 8) * AST + kk * 16 + 2 * tg],
                            psw[(g + 8) * AST + kk * 16 + 2 * tg + 1],
                            pah[1], pal[1]);
                split2_bf16(psw[g * AST + kk * 16 + 8 + 2 * tg],
                            psw[g * AST + kk * 16 + 8 + 2 * tg + 1],
                            pah[2], pal[2]);
                split2_bf16(psw[(g + 8) * AST + kk * 16 + 8 + 2 * tg],
                            psw[(g + 8) * AST + kk * 16 + 8 + 2 * tg + 1],
                            pah[3], pal[3]);
#pragma unroll
                for (int nt = 0; nt < 8; nt++) {
                    const int rb = (nt * 8 + g) * WST + kk * 8;
                    uint32_t bh[2], bl[2];
                    bh[0] = VThi[rb + tg];     bh[1] = VThi[rb + 4 + tg];
                    bl[0] = VTlo[rb + tg];     bl[1] = VTlo[rb + 4 + tg];
                    mma_bf16(o[nt], pah, bh);
                    mma_bf16(o[nt], pal, bh);
                    mma_bf16(o[nt], pah, bl);
                }
            }
        }
        __syncthreads();
    }

    // Epilogue: divide by l, write both rows.
    const float i0 = 1.f / l0, i1 = 1.f / l1;
    float* X0 = X + ((size_t)(b * S_ + qi0)) * DM + h * DK;
    float* X1 = X0 + 8 * DM;
#pragma unroll
    for (int nt = 0; nt < 8; nt++) {
        *(float2*)&X0[nt * 8 + 2 * tg] = make_float2(o[nt][0] * i0, o[nt][1] * i0);
        *(float2*)&X1[nt * 8 + 2 * tg] = make_float2(o[nt][2] * i1, o[nt][3] * i1);
    }
}

// ---------------------------------------------------------------------------
// Launch
// Inputs: 0:q 1:k 2:v 3:mask 4:wq 5:bq 6:wk 7:bk 8:wv 9:bv 10:wo 11:bo
// ---------------------------------------------------------------------------
extern "C" void kernel_launch(void* const* d_in, const int* in_sizes, int n_in,
                              void* d_out, int out_size)
{
    const float* q  = (const float*)d_in[0];
    const float* k  = (const float*)d_in[1];
    const float* v  = (const float*)d_in[2];
    const float* wq = (const float*)d_in[4];
    const float* bq = (const float*)d_in[5];
    const float* wk = (const float*)d_in[6];
    const float* bk = (const float*)d_in[7];
    const float* wv = (const float*)d_in[8];
    const float* bv = (const float*)d_in[9];
    const float* wo = (const float*)d_in[10];
    const float* bo = (const float*)d_in[11];
    float* out = (float*)d_out;

    float *gQ, *gK, *gV, *gX;
    cudaGetSymbolAddress((void**)&gQ, g_Q);
    cudaGetSymbolAddress((void**)&gK, g_K);
    cudaGetSymbolAddress((void**)&gV, g_V);
    cudaGetSymbolAddress((void**)&gX, g_X);

    cudaFuncSetAttribute(attn_tc,
                         cudaFuncAttributeMaxDynamicSharedMemorySize,
                         ATTN_TC_SMEM);

    const int M = B_ * S_;  // 4096

    dim3 qkvgrid(36, M / 64);        // (36, 64)
    gemm_qkv_tc<<<qkvgrid, 128>>>(q, k, v, wq, bq, wk, bk, wv, bv, gQ, gK, gV);

    dim3 agrid(S_ / 64, H_, B_);     // (32, 12, 2)
    attn_tc<<<agrid, 128, ATTN_TC_SMEM>>>(gQ, gK, gV, gX);

    dim3 wogrid(DM / 64, M / 64);    // (12, 64)
    gemm_wo_tc<<<wogrid, 128>>>(gX, wo, bo, out);
}

// round 17
// speedup vs baseline: 3.1525x; 1.0068x over previous
#include <cuda_runtime.h>
#include <cuda_bf16.h>
#include <cstdint>

// Problem constants
#define B_  2
#define S_  2048
#define DM  768
#define H_  12
#define DK  64

// Scratch (allocation-free rule: device globals)
__device__ float g_Q[B_ * S_ * DM];
__device__ float g_K[B_ * S_ * DM];
__device__ float g_V[B_ * S_ * DM];
__device__ float g_X[B_ * S_ * DM];

// ---------------------------------------------------------------------------
// BF16 m16n8k16 helpers (verified R14/R15): 3-term split
// ab = ah*bh + al*bh + ah*bl
// ---------------------------------------------------------------------------
__device__ __forceinline__ void mma_bf16(float* c, const uint32_t* a,
                                         const uint32_t* b) {
    asm volatile(
        "mma.sync.aligned.m16n8k16.row.col.f32.bf16.bf16.f32 "
        "{%0,%1,%2,%3}, {%4,%5,%6,%7}, {%8,%9}, {%0,%1,%2,%3};"
        : "+f"(c[0]), "+f"(c[1]), "+f"(c[2]), "+f"(c[3])
        : "r"(a[0]), "r"(a[1]), "r"(a[2]), "r"(a[3]),
          "r"(b[0]), "r"(b[1]));
}

__device__ __forceinline__ void split2_bf16(float x0, float x1,
                                            uint32_t& hi, uint32_t& lo) {
    __nv_bfloat162 h = __floats2bfloat162_rn(x0, x1);
    float r0 = x0 - __bfloat162float(h.x);
    float r1 = x1 - __bfloat162float(h.y);
    __nv_bfloat162 l = __floats2bfloat162_rn(r0, r1);
    hi = *reinterpret_cast<uint32_t*>(&h);
    lo = *reinterpret_cast<uint32_t*>(&l);
}

__device__ __forceinline__ void split1_bf16(float x, __nv_bfloat16& h,
                                            __nv_bfloat16& l) {
    h = __float2bfloat16_rn(x);
    l = __float2bfloat16_rn(x - __bfloat162float(h));
}

// ---------------------------------------------------------------------------
// BF16 tensor-core GEMM v2: C[M,N] = A[M,K] @ W[N,K]^T + bias[N]
// 128x128 CTA tile, 256 threads (8 warps, 4x2), warp tile 32x64, BK=16,
// double-buffered pre-split bf16x2 hi/lo smem tiles (48KB static).
// LDS/MMA = 1.0 (A frags amortized over nt=8, B frags shared across mt).
// ---------------------------------------------------------------------------
#define PADU 12

__device__ __forceinline__ void stage_f4(uint32_t* hiA, uint32_t* loA,
                                         int row, int c2, float4 v) {
    uint32_t h0, l0, h1, l1;
    split2_bf16(v.x, v.y, h0, l0);
    split2_bf16(v.z, v.w, h1, l1);
    hiA[row * PADU + c2]     = h0;
    hiA[row * PADU + c2 + 1] = h1;
    loA[row * PADU + c2]     = l0;
    loA[row * PADU + c2 + 1] = l1;
}

__device__ __forceinline__ void gemm_bf_body(
    const float* __restrict__ A, const float* __restrict__ W,
    const float* __restrict__ bias, float* __restrict__ C,
    int N, int K, int bm, int bn,
    uint32_t (*Ah)[128 * PADU], uint32_t (*Al)[128 * PADU],
    uint32_t (*Wh)[128 * PADU], uint32_t (*Wl)[128 * PADU])
{
    const int t    = threadIdx.x;
    const int lane = t & 31;
    const int wid  = t >> 5;           // 0..7
    const int wm   = (wid >> 1) * 32;  // warp M offset: 0/32/64/96
    const int wn   = (wid & 1) * 64;   // warp N offset: 0/64
    const int g    = lane >> 2;
    const int tg   = lane & 3;

    // Staging: thread covers row r, 8-float half (t&1) of the 16-wide k-slab.
    const int r  = t >> 1;             // 0..127
    const int cs = (t & 1) * 8;        // float col base
    const int c2 = (t & 1) * 4;        // u32 col base

    const float* Ap = A + (size_t)(bm + r) * K + cs;
    const float* Wp = W + (size_t)(bn + r) * K + cs;

    float acc[2][8][4];
#pragma unroll
    for (int i = 0; i < 2; i++)
#pragma unroll
        for (int j = 0; j < 8; j++)
#pragma unroll
            for (int c = 0; c < 4; c++) acc[i][j][c] = 0.f;

    // stage buffer 0
    stage_f4(Ah[0], Al[0], r, c2,     *(const float4*)(Ap));
    stage_f4(Ah[0], Al[0], r, c2 + 2, *(const float4*)(Ap + 4));
    stage_f4(Wh[0], Wl[0], r, c2,     *(const float4*)(Wp));
    stage_f4(Wh[0], Wl[0], r, c2 + 2, *(const float4*)(Wp + 4));
    __syncthreads();

    int cur = 0;
    for (int kt = 0; kt < K; kt += 16) {
        const bool has_next = (kt + 16) < K;
        float4 a0n, a1n, w0n, w1n;
        if (has_next) {
            a0n = *(const float4*)(Ap + kt + 16);
            a1n = *(const float4*)(Ap + kt + 20);
            w0n = *(const float4*)(Wp + kt + 16);
            w1n = *(const float4*)(Wp + kt + 20);
        }

        const uint32_t* ah_s = Ah[cur];
        const uint32_t* al_s = Al[cur];
        const uint32_t* wh_s = Wh[cur];
        const uint32_t* wl_s = Wl[cur];

        // A fragments: two m16k16 tiles (rows wm..wm+31).
        uint32_t ah[2][4], al[2][4];
#pragma unroll
        for (int mt = 0; mt < 2; mt++) {
            const int row = wm + mt * 16 + g;
            ah[mt][0] = ah_s[row * PADU + tg];
            ah[mt][1] = ah_s[(row + 8) * PADU + tg];
            ah[mt][2] = ah_s[row * PADU + 4 + tg];
            ah[mt][3] = ah_s[(row + 8) * PADU + 4 + tg];
            al[mt][0] = al_s[row * PADU + tg];
            al[mt][1] = al_s[(row + 8) * PADU + tg];
            al[mt][2] = al_s[row * PADU + 4 + tg];
            al[mt][3] = al_s[(row + 8) * PADU + 4 + tg];
        }
        // B fragments: 8 n8k16 tiles, each shared across both mt.
#pragma unroll
        for (int nt = 0; nt < 8; nt++) {
            const int n = wn + nt * 8 + g;
            uint32_t bh[2], bl[2];
            bh[0] = wh_s[n * PADU + tg];
            bh[1] = wh_s[n * PADU + 4 + tg];
            bl[0] = wl_s[n * PADU + tg];
            bl[1] = wl_s[n * PADU + 4 + tg];
#pragma unroll
            for (int mt = 0; mt < 2; mt++) {
                mma_bf16(acc[mt][nt], ah[mt], bh);
                mma_bf16(acc[mt][nt], al[mt], bh);
                mma_bf16(acc[mt][nt], ah[mt], bl);
            }
        }

        if (has_next) {
            const int nxt = cur ^ 1;
            stage_f4(Ah[nxt], Al[nxt], r, c2,     a0n);
            stage_f4(Ah[nxt], Al[nxt], r, c2 + 2, a1n);
            stage_f4(Wh[nxt], Wl[nxt], r, c2,     w0n);
            stage_f4(Wh[nxt], Wl[nxt], r, c2 + 2, w1n);
        }
        __syncthreads();
        cur ^= 1;
    }

    // Epilogue: bias + float2 stores (c0,c1 adjacent cols).
#pragma unroll
    for (int mt = 0; mt < 2; mt++) {
        const int row = bm + wm + mt * 16 + g;
#pragma unroll
        for (int nt = 0; nt < 8; nt++) {
            const int col = bn + wn + nt * 8 + tg * 2;
            const float b0 = bias[col], b1 = bias[col + 1];
            float2 v0 = { acc[mt][nt][0] + b0, acc[mt][nt][1] + b1 };
            float2 v1 = { acc[mt][nt][2] + b0, acc[mt][nt][3] + b1 };
            *(float2*)&C[(size_t)row * N + col]       = v0;
            *(float2*)&C[(size_t)(row + 8) * N + col] = v1;
        }
    }
}

// Fused QKV: blockIdx.x in [0,18): [0,6)->Q, [6,12)->K, [12,18)->V.
__global__ __launch_bounds__(256) void gemm_qkv_tc(
    const float* __restrict__ q, const float* __restrict__ k,
    const float* __restrict__ v,
    const float* __restrict__ wq, const float* __restrict__ bq,
    const float* __restrict__ wk, const float* __restrict__ bk,
    const float* __restrict__ wv, const float* __restrict__ bv,
    float* __restrict__ gQ, float* __restrict__ gK, float* __restrict__ gV)
{
    __shared__ uint32_t Ah[2][128 * PADU], Al[2][128 * PADU];
    __shared__ uint32_t Wh[2][128 * PADU], Wl[2][128 * PADU];

    const int bx  = blockIdx.x;
    const int sel = bx / 6;
    const int bn  = (bx % 6) * 128;
    const int bm  = blockIdx.y * 128;

    const float* A; const float* W; const float* bias; float* C;
    if (sel == 0)      { A = q; W = wq; bias = bq; C = gQ; }
    else if (sel == 1) { A = k; W = wk; bias = bk; C = gK; }
    else               { A = v; W = wv; bias = bv; C = gV; }

    gemm_bf_body(A, W, bias, C, DM, DM, bm, bn, Ah, Al, Wh, Wl);
}

__global__ __launch_bounds__(256) void gemm_wo_tc(
    const float* __restrict__ A, const float* __restrict__ W,
    const float* __restrict__ bias, float* __restrict__ C)
{
    __shared__ uint32_t Ah[2][128 * PADU], Al[2][128 * PADU];
    __shared__ uint32_t Wh[2][128 * PADU], Wl[2][128 * PADU];
    gemm_bf_body(A, W, bias, C, DM, DM,
                 blockIdx.y * 128, blockIdx.x * 128, Ah, Al, Wh, Wl);
}

// ---------------------------------------------------------------------------
// BF16 tensor-core causal flash attention (UNCHANGED from passing R15).
// ---------------------------------------------------------------------------
#define WST 36
#define AST 68
#define ATTN_TC_SMEM ((4 * 64 * WST) * 4 + (4 * 16 * AST) * 4)

__global__ __launch_bounds__(128) void attn_tc(
    const float* __restrict__ Q, const float* __restrict__ K,
    const float* __restrict__ V, float* __restrict__ X)
{
    extern __shared__ uint32_t sm[];
    uint32_t* Khi  = sm;
    uint32_t* Klo  = sm + 64 * WST;
    uint32_t* VThi = sm + 2 * 64 * WST;
    uint32_t* VTlo = sm + 3 * 64 * WST;
    float*    Ps   = (float*)(sm + 4 * 64 * WST);

    const int tid  = threadIdx.x;
    const int lane = tid & 31;
    const int wid  = tid >> 5;
    const int g    = lane >> 2;
    const int tg   = lane & 3;
    const int wm   = wid * 16;
    const int h    = blockIdx.y;
    const int b    = blockIdx.z;
    const int qblk = (int)gridDim.x - 1 - (int)blockIdx.x;   // LPT order
    const int q0   = qblk * 64;
    const int qi0  = q0 + wm + g;
    const int qi1  = qi0 + 8;
    float* psw = Ps + wid * (16 * AST);

    uint32_t qh[4][4], ql[4][4];
    {
        const float* Q0 = Q + ((size_t)(b * S_ + qi0)) * DM + h * DK;
        const float* Q1 = Q0 + 8 * DM;
#pragma unroll
        for (int kk = 0; kk < 4; kk++) {
            split2_bf16(Q0[kk * 16 + 2 * tg],     Q0[kk * 16 + 2 * tg + 1],
                        qh[kk][0], ql[kk][0]);
            split2_bf16(Q1[kk * 16 + 2 * tg],     Q1[kk * 16 + 2 * tg + 1],
                        qh[kk][1], ql[kk][1]);
            split2_bf16(Q0[kk * 16 + 8 + 2 * tg], Q0[kk * 16 + 8 + 2 * tg + 1],
                        qh[kk][2], ql[kk][2]);
            split2_bf16(Q1[kk * 16 + 8 + 2 * tg], Q1[kk * 16 + 8 + 2 * tg + 1],
                        qh[kk][3], ql[kk][3]);
        }
    }

    float o[8][4];
#pragma unroll
    for (int nt = 0; nt < 8; nt++)
#pragma unroll
        for (int c = 0; c < 4; c++) o[nt][c] = 0.f;
    float m0 = -1e30f, m1 = -1e30f, l0 = 0.f, l1 = 0.f;

    for (int c0 = 0; c0 < q0 + 64; c0 += 64) {
        const float4* kb4 = (const float4*)(K + ((size_t)(b * S_ + c0)) * DM + h * DK);
        const float4* vb4 = (const float4*)(V + ((size_t)(b * S_ + c0)) * DM + h * DK);

#pragma unroll
        for (int i = 0; i < 8; i++) {
            const int idx = tid + i * 128;
            const int j   = idx >> 4;
            const int c4  = idx & 15;
            float4 kv = kb4[(size_t)j * (DM / 4) + c4];
            uint32_t h0, l0w, h1, l1w;
            split2_bf16(kv.x, kv.y, h0, l0w);
            split2_bf16(kv.z, kv.w, h1, l1w);
            Khi[j * WST + 2 * c4]     = h0;
            Khi[j * WST + 2 * c4 + 1] = h1;
            Klo[j * WST + 2 * c4]     = l0w;
            Klo[j * WST + 2 * c4 + 1] = l1w;
        }
        __nv_bfloat16* VThib = (__nv_bfloat16*)VThi;
        __nv_bfloat16* VTlob = (__nv_bfloat16*)VTlo;
#pragma unroll
        for (int i = 0; i < 8; i++) {
            const int idx = tid + i * 128;
            const int j   = idx & 63;
            const int cg  = idx >> 6;
            float4 vv = vb4[(size_t)j * (DM / 4) + cg];
            __nv_bfloat16 hb, lb;
            split1_bf16(vv.x, hb, lb);
            VThib[(cg * 4 + 0) * (2 * WST) + j] = hb;
            VTlob[(cg * 4 + 0) * (2 * WST) + j] = lb;
            split1_bf16(vv.y, hb, lb);
            VThib[(cg * 4 + 1) * (2 * WST) + j] = hb;
            VTlob[(cg * 4 + 1) * (2 * WST) + j] = lb;
            split1_bf16(vv.z, hb, lb);
            VThib[(cg * 4 + 2) * (2 * WST) + j] = hb;
            VTlob[(cg * 4 + 2) * (2 * WST) + j] = lb;
            split1_bf16(vv.w, hb, lb);
            VThib[(cg * 4 + 3) * (2 * WST) + j] = hb;
            VTlob[(cg * 4 + 3) * (2 * WST) + j] = lb;
        }
        __syncthreads();

        if (c0 < q0 + wm + 16) {
            float s[8][4];
#pragma unroll
            for (int nt = 0; nt < 8; nt++)
#pragma unroll
                for (int c = 0; c < 4; c++) s[nt][c] = 0.f;

#pragma unroll
            for (int kk = 0; kk < 4; kk++) {
#pragma unroll
                for (int nt = 0; nt < 8; nt++) {
                    const int rb = (nt * 8 + g) * WST + kk * 8;
                    uint32_t bh[2], bl[2];
                    bh[0] = Khi[rb + tg];     bh[1] = Khi[rb + 4 + tg];
                    bl[0] = Klo[rb + tg];     bl[1] = Klo[rb + 4 + tg];
                    mma_bf16(s[nt], qh[kk], bh);
                    mma_bf16(s[nt], ql[kk], bh);
                    mma_bf16(s[nt], qh[kk], bl);
                }
            }

            const bool full = (c0 + 63 <= q0 + wm);
#pragma unroll
            for (int nt = 0; nt < 8; nt++) {
                s[nt][0] *= 0.125f; s[nt][1] *= 0.125f;
                s[nt][2] *= 0.125f; s[nt][3] *= 0.125f;
                if (!full) {
                    const int jg = c0 + nt * 8 + 2 * tg;
                    if (jg     > qi0) s[nt][0] = -1e30f;
                    if (jg + 1 > qi0) s[nt][1] = -1e30f;
                    if (jg     > qi1) s[nt][2] = -1e30f;
                    if (jg + 1 > qi1) s[nt][3] = -1e30f;
                }
            }

            float mx0 = -1e30f, mx1 = -1e30f;
#pragma unroll
            for (int nt = 0; nt < 8; nt++) {
                mx0 = fmaxf(mx0, fmaxf(s[nt][0], s[nt][1]));
                mx1 = fmaxf(mx1, fmaxf(s[nt][2], s[nt][3]));
            }
            mx0 = fmaxf(mx0, __shfl_xor_sync(0xffffffffu, mx0, 1));
            mx0 = fmaxf(mx0, __shfl_xor_sync(0xffffffffu, mx0, 2));
            mx1 = fmaxf(mx1, __shfl_xor_sync(0xffffffffu, mx1, 1));
            mx1 = fmaxf(mx1, __shfl_xor_sync(0xffffffffu, mx1, 2));

            const float nm0 = fmaxf(m0, mx0), nm1 = fmaxf(m1, mx1);
            const float cr0 = __expf(m0 - nm0), cr1 = __expf(m1 - nm1);
            m0 = nm0; m1 = nm1;
            l0 *= cr0; l1 *= cr1;

            float ls0 = 0.f, ls1 = 0.f;
#pragma unroll
            for (int nt = 0; nt < 8; nt++) {
                const float p0 = __expf(s[nt][0] - m0);
                const float p1 = __expf(s[nt][1] - m0);
                const float p2 = __expf(s[nt][2] - m1);
                const float p3 = __expf(s[nt][3] - m1);
                ls0 += p0 + p1; ls1 += p2 + p3;
                o[nt][0] *= cr0; o[nt][1] *= cr0;
                o[nt][2] *= cr1; o[nt][3] *= cr1;
                *(float2*)&psw[g * AST + nt * 8 + 2 * tg]       = make_float2(p0, p1);
                *(float2*)&psw[(g + 8) * AST + nt * 8 + 2 * tg] = make_float2(p2, p3);
            }
            ls0 += __shfl_xor_sync(0xffffffffu, ls0, 1);
            ls0 += __shfl_xor_sync(0xffffffffu, ls0, 2);
            ls1 += __shfl_xor_sync(0xffffffffu, ls1, 1);
            ls1 += __shfl_xor_sync(0xffffffffu, ls1, 2);
            l0 += ls0; l1 += ls1;
            __syncwarp();

#pragma unroll
            for (int kk = 0; kk < 4; kk++) {
                uint32_t pah[4], pal[4];
                split2_bf16(psw[g * AST + kk * 16 + 2 * tg],
                            psw[g * AST + kk * 16 + 2 * tg + 1],
                            pah[0], pal[0]);
                split2_bf16(psw[(g + 8) * AST + kk * 16 + 2 * tg],
                            psw[(g + 8) * AST + kk * 16 + 2 * tg + 1],
                            pah[1], pal[1]);
                split2_bf16(psw[g * AST + kk * 16 + 8 + 2 * tg],
                            psw[g * AST + kk * 16 + 8 + 2 * tg + 1],
                            pah[2], pal[2]);
                split2_bf16(psw[(g + 8) * AST + kk * 16 + 8 + 2 * tg],
                            psw[(g + 8) * AST + kk * 16 + 8 + 2 * tg + 1],
                            pah[3], pal[3]);
#pragma unroll
                for (int nt = 0; nt < 8; nt++) {
                    const int rb = (nt * 8 + g) * WST + kk * 8;
                    uint32_t bh[2], bl[2];
                    bh[0] = VThi[rb + tg];     bh[1] = VThi[rb + 4 + tg];
                    bl[0] = VTlo[rb + tg];     bl[1] = VTlo[rb + 4 + tg];
                    mma_bf16(o[nt], pah, bh);
                    mma_bf16(o[nt], pal, bh);
                    mma_bf16(o[nt], pah, bl);
                }
            }
        }
        __syncthreads();
    }

    const float i0 = 1.f / l0, i1 = 1.f / l1;
    float* X0 = X + ((size_t)(b * S_ + qi0)) * DM + h * DK;
    float* X1 = X0 + 8 * DM;
#pragma unroll
    for (int nt = 0; nt < 8; nt++) {
        *(float2*)&X0[nt * 8 + 2 * tg] = make_float2(o[nt][0] * i0, o[nt][1] * i0);
        *(float2*)&X1[nt * 8 + 2 * tg] = make_float2(o[nt][2] * i1, o[nt][3] * i1);
    }
}

// ---------------------------------------------------------------------------
// Launch
// Inputs: 0:q 1:k 2:v 3:mask 4:wq 5:bq 6:wk 7:bk 8:wv 9:bv 10:wo 11:bo
// ---------------------------------------------------------------------------
extern "C" void kernel_launch(void* const* d_in, const int* in_sizes, int n_in,
                              void* d_out, int out_size)
{
    const float* q  = (const float*)d_in[0];
    const float* k  = (const float*)d_in[1];
    const float* v  = (const float*)d_in[2];
    const float* wq = (const float*)d_in[4];
    const float* bq = (const float*)d_in[5];
    const float* wk = (const float*)d_in[6];
    const float* bk = (const float*)d_in[7];
    const float* wv = (const float*)d_in[8];
    const float* bv = (const float*)d_in[9];
    const float* wo = (const float*)d_in[10];
    const float* bo = (const float*)d_in[11];
    float* out = (float*)d_out;

    float *gQ, *gK, *gV, *gX;
    cudaGetSymbolAddress((void**)&gQ, g_Q);
    cudaGetSymbolAddress((void**)&gK, g_K);
    cudaGetSymbolAddress((void**)&gV, g_V);
    cudaGetSymbolAddress((void**)&gX, g_X);

    cudaFuncSetAttribute(attn_tc,
                         cudaFuncAttributeMaxDynamicSharedMemorySize,
                         ATTN_TC_SMEM);

    const int M = B_ * S_;  // 4096

    dim3 qkvgrid(18, M / 128);       // (18, 32): 3 x 6 n-tiles, 32 m-tiles
    gemm_qkv_tc<<<qkvgrid, 256>>>(q, k, v, wq, bq, wk, bk, wv, bv, gQ, gK, gV);

    dim3 agrid(S_ / 64, H_, B_);     // (32, 12, 2)
    attn_tc<<<agrid, 128, ATTN_TC_SMEM>>>(gQ, gK, gV, gX);

    dim3 wogrid(DM / 128, M / 128);  // (6, 32)
    gemm_wo_tc<<<wogrid, 256>>>(gX, wo, bo, out);
}